// round 5
// baseline (speedup 1.0000x reference)
#include <cuda_runtime.h>
#include <cuda_bf16.h>
#include <math.h>
#include <stdint.h>

static constexpr int BB = 64;
static constexpr int LL = 2048;
static constexpr int HH = 256;
static constexpr int VV = 32000;
static constexpr int TT = LL - 1;
static constexpr float BETA = 0.9f;
static constexpr float OMB  = 0.1f;
static constexpr int CH = 32;

// ---------------- scratch (device globals) ----------------
__device__ float g_h [(size_t)BB*LL*HH];               // x then LayerNorm(h)
__device__ __nv_bfloat16 g_ah [(size_t)BB*LL*HH];      // gathered embed hi
__device__ __nv_bfloat16 g_al [(size_t)BB*LL*HH];      // gathered embed lo
__device__ __nv_bfloat16 g_ffh[(size_t)BB*LL*2*HH];    // relu(e@W1+b1) hi
__device__ __nv_bfloat16 g_ffl[(size_t)BB*LL*2*HH];    // lo
__device__ __nv_bfloat16 g_w1h[512*256], g_w1l[512*256];   // W1^T [N=512][K=256]
__device__ __nv_bfloat16 g_w2h[256*512], g_w2l[256*512];   // W2^T [N=256][K=512]
__device__ float g_M [(size_t)BB*HH*HH];
__device__ float g_y [BB*HH];
__device__ float g_y2[BB*HH];

// ---------------- helpers ----------------
#define SWZ(o) ((o) ^ (((o) >> 3) & 0x70))

__device__ __forceinline__ uint32_t smem_u32(const void* p) {
    uint32_t a;
    asm("{ .reg .u64 t; cvta.to.shared.u64 t, %1; cvt.u32.u64 %0, t; }" : "=r"(a) : "l"(p));
    return a;
}
__device__ __forceinline__ uint32_t pack2(__nv_bfloat16 a, __nv_bfloat16 b) {
    __nv_bfloat162 t = __halves2bfloat162(a, b);
    return *reinterpret_cast<uint32_t*>(&t);
}
__device__ __forceinline__ void ldsm_x4(uint32_t* r, uint32_t addr) {
    asm volatile("ldmatrix.sync.aligned.m8n8.x4.shared.b16 {%0,%1,%2,%3}, [%4];"
        : "=r"(r[0]), "=r"(r[1]), "=r"(r[2]), "=r"(r[3]) : "r"(addr));
}
__device__ __forceinline__ void mma_bf16(float* d, const uint32_t* a, uint32_t b0, uint32_t b1) {
    asm volatile("mma.sync.aligned.m16n8k16.row.col.f32.bf16.bf16.f32 "
        "{%0,%1,%2,%3}, {%4,%5,%6,%7}, {%8,%9}, {%0,%1,%2,%3};"
        : "+f"(d[0]), "+f"(d[1]), "+f"(d[2]), "+f"(d[3])
        : "r"(a[0]), "r"(a[1]), "r"(a[2]), "r"(a[3]), "r"(b0), "r"(b1));
}
__device__ __forceinline__ void cp16(uint32_t dst, const void* src) {
    asm volatile("cp.async.cg.shared.global [%0], [%1], 16;" :: "r"(dst), "l"(src));
}

// ---------------- 0a. weight transpose + bf16 split ----------------
__global__ void k_prep(const float* __restrict__ W1, const float* __restrict__ W2) {
    int idx = blockIdx.x * blockDim.x + threadIdx.x;   // 0 .. 131071
    {   // W1t [n=512][k=256] = W1[k][n]
        int n = idx >> 8, k = idx & 255;
        float w = W1[k * 512 + n];
        __nv_bfloat16 h = __float2bfloat16(w);
        g_w1h[idx] = h;
        g_w1l[idx] = __float2bfloat16(w - __bfloat162float(h));
    }
    {   // W2t [n=256][k=512] = W2[k][n]
        int n = idx >> 9, k = idx & 511;
        float w = W2[k * 256 + n];
        __nv_bfloat16 h = __float2bfloat16(w);
        g_w2h[idx] = h;
        g_w2l[idx] = __float2bfloat16(w - __bfloat162float(h));
    }
}

// ---------------- 0b. embedding gather + bf16 split ----------------
__global__ void k_split(const int* __restrict__ seq, const float* __restrict__ embed) {
    size_t idx = (size_t)blockIdx.x * blockDim.x + threadIdx.x;   // over B*L*64 quads
    int row = (int)(idx >> 6), q = (int)(idx & 63);
    int tok = seq[row];
    float4 v = ((const float4*)embed)[(size_t)tok * 64 + q];
    __nv_bfloat16 h0 = __float2bfloat16(v.x), h1 = __float2bfloat16(v.y);
    __nv_bfloat16 h2 = __float2bfloat16(v.z), h3 = __float2bfloat16(v.w);
    ((uint2*)g_ah)[idx] = make_uint2(pack2(h0, h1), pack2(h2, h3));
    ((uint2*)g_al)[idx] = make_uint2(
        pack2(__float2bfloat16(v.x - __bfloat162float(h0)),
              __float2bfloat16(v.y - __bfloat162float(h1))),
        pack2(__float2bfloat16(v.z - __bfloat162float(h2)),
              __float2bfloat16(v.w - __bfloat162float(h3))));
}

// ---------------- 1+2. FFN GEMMs, HMMA + cp.async 2-stage pipeline ----------------
// PHASE 1: ff = relu(A @ W1 + b1) -> g_ffh/g_ffl   (M=131072, N=512, K=256)
// PHASE 2: x  = ff @ W2 + b2 + e  -> g_h           (M=131072, N=256, K=512)
// CTA tile 128x128, 8 warps (2m x 4n), warp tile 64x32, K chunk 64 (SW128 smem).
static constexpr int FFN_SMEM = 1024 + 2 * 65536;   // 132096 B

struct FragAcc { float a[4][4][4]; };

__device__ __forceinline__ void ffn_compute(
    uint32_t aHI, uint32_t aLO, uint32_t bHI, uint32_t bLO,
    int wm, int wn, int lid, float (&acc)[4][4][4])
{
    #pragma unroll
    for (int ks = 0; ks < 4; ++ks) {
        uint32_t colA = ks * 32 + ((lid >> 4) << 4);
        uint32_t ah[4][4];
        #pragma unroll
        for (int mf = 0; mf < 4; ++mf) {
            uint32_t row = wm * 64 + mf * 16 + (lid & 15);
            ldsm_x4(ah[mf], aHI + SWZ(row * 128 + colA));
        }
        uint32_t bh[2][4], bl[2][4];
        #pragma unroll
        for (int nf = 0; nf < 2; ++nf) {
            uint32_t row = wn * 32 + nf * 16 + ((lid >> 4) << 3) + (lid & 7);
            uint32_t colB = ks * 32 + (((lid >> 3) & 1) << 4);
            ldsm_x4(bh[nf], bHI + SWZ(row * 128 + colB));
            ldsm_x4(bl[nf], bLO + SWZ(row * 128 + colB));
        }
        #pragma unroll
        for (int mf = 0; mf < 4; ++mf)
            #pragma unroll
            for (int nf = 0; nf < 2; ++nf)
                #pragma unroll
                for (int j = 0; j < 2; ++j) {
                    mma_bf16(acc[mf][nf*2+j], ah[mf], bh[nf][j*2], bh[nf][j*2+1]);
                    mma_bf16(acc[mf][nf*2+j], ah[mf], bl[nf][j*2], bl[nf][j*2+1]);
                }
        uint32_t al[4][4];
        #pragma unroll
        for (int mf = 0; mf < 4; ++mf) {
            uint32_t row = wm * 64 + mf * 16 + (lid & 15);
            ldsm_x4(al[mf], aLO + SWZ(row * 128 + colA));
        }
        #pragma unroll
        for (int mf = 0; mf < 4; ++mf)
            #pragma unroll
            for (int nf = 0; nf < 2; ++nf)
                #pragma unroll
                for (int j = 0; j < 2; ++j)
                    mma_bf16(acc[mf][nf*2+j], al[mf], bh[nf][j*2], bh[nf][j*2+1]);
    }
}

template<int PHASE>
__global__ __launch_bounds__(256) void k_ffn(
    const int* __restrict__ seq, const float* __restrict__ embed,
    const float* __restrict__ bias)
{
    constexpr int K   = (PHASE == 1) ? HH : 2 * HH;
    constexpr int NC  = K / 64;
    constexpr int ARS = (PHASE == 1) ? HH : 2 * HH;   // A row stride (elems)

    extern __shared__ char sm[];
    int*   sseq  = (int*)sm;              // 128 ints (phase 2 only)
    float* sbias = (float*)(sm + 512);    // 128 floats
    char* st0 = sm + 1024;
    char* st1 = sm + 1024 + 65536;

    const int tid = threadIdx.x, wid = tid >> 5, lid = tid & 31;
    const int wm = wid & 1, wn = wid >> 1;
    const int m0  = blockIdx.y * 128;
    const int nb0 = blockIdx.x * 128;

    const __nv_bfloat16* Ah = (PHASE == 1) ? g_ah  : g_ffh;
    const __nv_bfloat16* Al = (PHASE == 1) ? g_al  : g_ffl;
    const __nv_bfloat16* Wh = (PHASE == 1) ? g_w1h : g_w2h;
    const __nv_bfloat16* Wl = (PHASE == 1) ? g_w1l : g_w2l;

    if (tid < 128) {
        sbias[tid] = bias[nb0 + tid];
        if (PHASE == 2) sseq[tid] = seq[m0 + tid];
    }

    // issue loads of chunk c into stage st
    const int a_row = tid >> 1, a_half = tid & 1;
    const int b_row = tid & 127, b_sel = tid >> 7;
    auto issue = [&](int c, char* st) {
        int k0 = c * 64;
        uint32_t aH = smem_u32(st), aL = aH + 16384, bH = aL + 16384, bL = bH + 16384;
        const char* asrcH = (const char*)(Ah + (size_t)(m0 + a_row) * ARS + k0) + a_half * 64;
        const char* asrcL = (const char*)(Al + (size_t)(m0 + a_row) * ARS + k0) + a_half * 64;
        #pragma unroll
        for (int j = 0; j < 4; ++j) {
            uint32_t off = SWZ((uint32_t)(a_row * 128 + a_half * 64 + j * 16));
            cp16(aH + off, asrcH + j * 16);
            cp16(aL + off, asrcL + j * 16);
        }
        const __nv_bfloat16* w = b_sel ? Wl : Wh;
        uint32_t bb = b_sel ? bL : bH;
        const char* bsrc = (const char*)(w + (size_t)(nb0 + b_row) * K + k0);
        #pragma unroll
        for (int j = 0; j < 8; ++j)
            cp16(bb + SWZ((uint32_t)(b_row * 128 + j * 16)), bsrc + j * 16);
        asm volatile("cp.async.commit_group;" ::: "memory");
    };

    float acc[4][4][4];
    #pragma unroll
    for (int a = 0; a < 4; ++a)
        #pragma unroll
        for (int b = 0; b < 4; ++b)
            #pragma unroll
            for (int c = 0; c < 4; ++c) acc[a][b][c] = 0.f;

    issue(0, st0);
    for (int c = 0; c < NC; ++c) {
        char* cur = (c & 1) ? st1 : st0;
        if (c + 1 < NC) {
            issue(c + 1, ((c + 1) & 1) ? st1 : st0);
            asm volatile("cp.async.wait_group 1;" ::: "memory");
        } else {
            asm volatile("cp.async.wait_group 0;" ::: "memory");
        }
        __syncthreads();
        uint32_t aH = smem_u32(cur);
        ffn_compute(aH, aH + 16384, aH + 32768, aH + 49152, wm, wn, lid, acc);
        __syncthreads();
    }

    // ---- epilogue: stage to smem, then coalesced global writes ----
    const int qm = lid >> 2, qn = (lid & 3) * 2;
    if (PHASE == 1) {
        uint32_t* SH = (uint32_t*)(sm + 1024);           // [128][64] packed bf16x2
        uint32_t* SL = SH + 8192;
        #pragma unroll
        for (int mf = 0; mf < 4; ++mf)
            #pragma unroll
            for (int nf = 0; nf < 2; ++nf)
                #pragma unroll
                for (int j = 0; j < 2; ++j) {
                    const float* d = acc[mf][nf*2+j];
                    int nl = wn * 32 + nf * 16 + j * 8 + qn;
                    #pragma unroll
                    for (int hh = 0; hh < 2; ++hh) {
                        int ml = wm * 64 + mf * 16 + qm + hh * 8;
                        float v0 = fmaxf(d[hh*2+0] + sbias[nl],   0.f);
                        float v1 = fmaxf(d[hh*2+1] + sbias[nl+1], 0.f);
                        __nv_bfloat16 h0 = __float2bfloat16(v0);
                        __nv_bfloat16 h1 = __float2bfloat16(v1);
                        SH[ml * 64 + (nl >> 1)] = pack2(h0, h1);
                        SL[ml * 64 + (nl >> 1)] =
                            pack2(__float2bfloat16(v0 - __bfloat162float(h0)),
                                  __float2bfloat16(v1 - __bfloat162float(h1)));
                    }
                }
        __syncthreads();
        int row = tid >> 1, part = tid & 1;
        const uint4* shp = (const uint4*)SH;
        const uint4* slp = (const uint4*)SL;
        uint4* gh = (uint4*)(g_ffh + (size_t)(m0 + row) * 512 + nb0);
        uint4* gl = (uint4*)(g_ffl + (size_t)(m0 + row) * 512 + nb0);
        #pragma unroll
        for (int j = 0; j < 8; ++j) {
            int q = part * 8 + j;
            gh[q] = shp[row * 16 + q];
            gl[q] = slp[row * 16 + q];
        }
    } else {
        float* SF = (float*)(sm + 1024);                 // [128][128] f32
        #pragma unroll
        for (int mf = 0; mf < 4; ++mf)
            #pragma unroll
            for (int nf = 0; nf < 2; ++nf)
                #pragma unroll
                for (int j = 0; j < 2; ++j) {
                    const float* d = acc[mf][nf*2+j];
                    int nl = wn * 32 + nf * 16 + j * 8 + qn;
                    #pragma unroll
                    for (int hh = 0; hh < 2; ++hh) {
                        int ml = wm * 64 + mf * 16 + qm + hh * 8;
                        SF[ml * 128 + nl]     = d[hh*2+0] + sbias[nl];
                        SF[ml * 128 + nl + 1] = d[hh*2+1] + sbias[nl+1];
                    }
                }
        __syncthreads();
        int row = tid >> 1, part = tid & 1;
        int tok = sseq[row];
        const float4* ep = (const float4*)(embed + (size_t)tok * HH + nb0);
        const float4* sfp = (const float4*)(SF + row * 128);
        float4* gp = (float4*)(g_h + (size_t)(m0 + row) * HH + nb0);
        #pragma unroll
        for (int j = 0; j < 16; ++j) {
            int c4 = part * 16 + j;
            float4 f = sfp[c4];
            float4 e = ep[c4];
            f.x += e.x; f.y += e.y; f.z += e.z; f.w += e.w;
            gp[c4] = f;
        }
    }
}

// ---------------- 3. LayerNorm: one warp per row, float4 ----------------
__global__ void k_ln(const float* __restrict__ gamma, const float* __restrict__ beta_ln) {
    int warp = threadIdx.x >> 5, lane = threadIdx.x & 31;
    size_t row = (size_t)blockIdx.x * 8 + warp;
    float4* xp = (float4*)(g_h + row * HH);
    float4 a = xp[lane * 2];
    float4 b = xp[lane * 2 + 1];
    float s = a.x + a.y + a.z + a.w + b.x + b.y + b.z + b.w;
    #pragma unroll
    for (int o = 16; o; o >>= 1) s += __shfl_xor_sync(0xffffffffu, s, o);
    float mu = s * (1.0f / HH);
    float dx[8] = {a.x-mu, a.y-mu, a.z-mu, a.w-mu, b.x-mu, b.y-mu, b.z-mu, b.w-mu};
    float v = 0.f;
    #pragma unroll
    for (int q = 0; q < 8; ++q) v += dx[q] * dx[q];
    #pragma unroll
    for (int o = 16; o; o >>= 1) v += __shfl_xor_sync(0xffffffffu, v, o);
    float inv = rsqrtf(v * (1.0f / HH) + 1e-5f);
    float4 g0 = ((const float4*)gamma)[lane * 2];
    float4 g1 = ((const float4*)gamma)[lane * 2 + 1];
    float4 t0 = ((const float4*)beta_ln)[lane * 2];
    float4 t1 = ((const float4*)beta_ln)[lane * 2 + 1];
    float4 o0, o1;
    o0.x = dx[0]*inv*g0.x + t0.x; o0.y = dx[1]*inv*g0.y + t0.y;
    o0.z = dx[2]*inv*g0.z + t0.z; o0.w = dx[3]*inv*g0.w + t0.w;
    o1.x = dx[4]*inv*g1.x + t1.x; o1.y = dx[5]*inv*g1.y + t1.y;
    o1.z = dx[6]*inv*g1.z + t1.z; o1.w = dx[7]*inv*g1.w + t1.w;
    xp[lane * 2]     = o0;
    xp[lane * 2 + 1] = o1;
}

// ---------------- 4. chunked momentum delta-rule scan ----------------
static constexpr int SCAN_SMEM_FLOATS = 128*257 + CH*257 + CH*128 + CH*CH + CH + 40;
static constexpr int SCAN_SMEM_BYTES  = SCAN_SMEM_FLOATS * 4;

__global__ __launch_bounds__(256, 1) void k_scan() {
    extern __shared__ float smf[];
    float* sM  = smf;
    float* sK  = sM + 128*257;
    float* sD  = sK + CH*257;
    float* sA  = sD + CH*128;
    float* sc  = sA + CH*CH;
    float* spw = sc + CH;

    int tid = threadIdx.x;
    int b   = blockIdx.x >> 1;
    int r0  = (blockIdx.x & 1) * 128;

    for (int i = tid; i < 128*257; i += 256) sM[i] = 0.f;
    if (tid == 0) {
        spw[0] = 1.f;
        for (int i = 1; i <= CH; ++i) spw[i] = spw[i-1] * BETA;
    }
    __syncthreads();

    const int u_ig = tid >> 3;
    const int u_tg = tid & 7;
    const int m_ig = tid & 15;
    const int m_jg = tid >> 4;

    const float* hb = g_h + (size_t)b * LL * HH;

    for (int t0 = 0; t0 < TT; t0 += CH) {
        int Cc = min(CH, TT - t0);
        __syncthreads();

        for (int idx = tid; idx < Cc * 64; idx += 256) {
            int lt = idx >> 6, q = idx & 63;
            float4 v = *(const float4*)(hb + (size_t)(t0 + lt) * HH + q * 4);
            float* dst = sK + lt*257 + q*4;
            dst[0] = v.x; dst[1] = v.y; dst[2] = v.z; dst[3] = v.w;
        }
        __syncthreads();

        int P = Cc * (Cc + 1) / 2;
        for (int p = tid; p < P; p += 256) {
            int t = (int)((sqrtf(8.f * p + 1.f) - 1.f) * 0.5f);
            while ((t + 1) * (t + 2) / 2 <= p) ++t;
            while (t * (t + 1) / 2 > p) --t;
            int s = p - t * (t + 1) / 2;
            const float* kt = sK + t*257;
            const float* ks = sK + s*257;
            float dot = 0.f;
            #pragma unroll 8
            for (int j = 0; j < HH; ++j) dot += kt[j] * ks[j];
            if (s == t) sc[t] = dot;
            else        sA[t*CH + s] = dot;
        }
        __syncthreads();
        if (tid < Cc) sc[tid] = 1.0f / (sc[tid] + 1e-6f);
        __syncthreads();
        for (int p = tid; p < P; p += 256) {
            int t = (int)((sqrtf(8.f * p + 1.f) - 1.f) * 0.5f);
            while ((t + 1) * (t + 2) / 2 <= p) ++t;
            while (t * (t + 1) / 2 > p) --t;
            int s = p - t * (t + 1) / 2;
            if (s < t) sA[t*CH + s] *= sc[t] * OMB * spw[t - 1 - s];
        }
        __syncthreads();

        {
            int i0 = u_ig * 4, lt0 = u_tg * 4;
            float acc[4][4];
            #pragma unroll
            for (int r = 0; r < 4; ++r)
                #pragma unroll
                for (int c = 0; c < 4; ++c) acc[r][c] = 0.f;
            #pragma unroll 4
            for (int j = 0; j < HH; ++j) {
                float a0 = sM[(i0+0)*257 + j], a1 = sM[(i0+1)*257 + j];
                float a2 = sM[(i0+2)*257 + j], a3 = sM[(i0+3)*257 + j];
                float b0 = sK[(lt0+0)*257 + j], b1 = sK[(lt0+1)*257 + j];
                float b2 = sK[(lt0+2)*257 + j], b3 = sK[(lt0+3)*257 + j];
                acc[0][0] += a0*b0; acc[0][1] += a0*b1; acc[0][2] += a0*b2; acc[0][3] += a0*b3;
                acc[1][0] += a1*b0; acc[1][1] += a1*b1; acc[1][2] += a1*b2; acc[1][3] += a1*b3;
                acc[2][0] += a2*b0; acc[2][1] += a2*b1; acc[2][2] += a2*b2; acc[2][3] += a2*b3;
                acc[3][0] += a3*b0; acc[3][1] += a3*b1; acc[3][2] += a3*b2; acc[3][3] += a3*b3;
            }
            #pragma unroll
            for (int c = 0; c < 4; ++c) {
                int lt = lt0 + c;
                if (lt < Cc) {
                    float coef = sc[lt] * spw[lt];
                    #pragma unroll
                    for (int r = 0; r < 4; ++r) {
                        int i = i0 + r;
                        sD[lt*128 + i] = sK[lt*257 + r0 + i] - coef * acc[r][c];
                    }
                }
            }
        }
        __syncthreads();

        {
            int i  = tid & 127;
            int tg = tid >> 7;
            for (int s = 0; s < Cc - 1; ++s) {
                __syncthreads();
                float ds = sD[s*128 + i];
                for (int t = s + 1 + tg; t < Cc; t += 2)
                    sD[t*128 + i] -= sA[t*CH + s] * ds;
            }
            __syncthreads();
        }

        {
            float bc = spw[Cc];
            int i0 = m_ig * 8, j0 = m_jg * 16;
            float acc[8][16];
            #pragma unroll
            for (int r = 0; r < 8; ++r)
                #pragma unroll
                for (int c = 0; c < 16; ++c)
                    acc[r][c] = sM[(i0+r)*257 + j0 + c] * bc;
            for (int s = 0; s < Cc; ++s) {
                float w = OMB * spw[Cc - 1 - s];
                float4 d0 = *(const float4*)(sD + s*128 + i0);
                float4 d1 = *(const float4*)(sD + s*128 + i0 + 4);
                float dr[8] = {d0.x*w, d0.y*w, d0.z*w, d0.w*w,
                               d1.x*w, d1.y*w, d1.z*w, d1.w*w};
                #pragma unroll
                for (int c = 0; c < 16; ++c) {
                    float kv = sK[s*257 + j0 + c];
                    #pragma unroll
                    for (int r = 0; r < 8; ++r) acc[r][c] += dr[r] * kv;
                }
            }
            #pragma unroll
            for (int r = 0; r < 8; ++r)
                #pragma unroll
                for (int c = 0; c < 16; ++c)
                    sM[(i0+r)*257 + j0 + c] = acc[r][c];
        }
    }

    __syncthreads();
    for (int idx = tid; idx < 128 * HH; idx += 256) {
        int i = idx >> 8, j = idx & 255;
        g_M[((size_t)b * HH + r0 + i) * HH + j] = sM[i*257 + j];
    }
}

// ---------------- 5. readout: y = M h_last ----------------
__global__ void k_read1() {
    int b = blockIdx.x;
    int tid = threadIdx.x;
    __shared__ float hl[HH];
    hl[tid] = g_h[((size_t)b * LL + (LL - 1)) * HH + tid];
    __syncthreads();
    int w = tid >> 5, lane = tid & 31;
    for (int i = w; i < HH; i += 8) {
        const float* Mr = g_M + ((size_t)b * HH + i) * HH;
        float s = 0.f;
        #pragma unroll
        for (int j = lane; j < HH; j += 32) s += Mr[j] * hl[j];
        #pragma unroll
        for (int o = 16; o; o >>= 1) s += __shfl_xor_sync(0xffffffffu, s, o);
        if (lane == 0) g_y[b * HH + i] = s;
    }
}

// ---------------- 6. y2 = y @ rp_W + rp_b ----------------
__global__ void k_read2(const float* __restrict__ rp_W, const float* __restrict__ rp_b) {
    int b = blockIdx.x, n = threadIdx.x;
    __shared__ float ys[HH];
    ys[n] = g_y[b * HH + n];
    __syncthreads();
    float acc = rp_b[n];
    #pragma unroll 4
    for (int k = 0; k < HH; ++k) acc += ys[k] * rp_W[k * HH + n];
    g_y2[b * HH + n] = acc;
}

// ---------------- 7. out = y2 @ out_W + out_b ----------------
static constexpr int OUT_SMEM_BYTES = (HH * 128 + BB * 257) * 4;

__global__ __launch_bounds__(256) void k_out(
    const float* __restrict__ out_W, const float* __restrict__ out_b,
    float* __restrict__ out)
{
    extern __shared__ float smf[];
    float* sW  = smf;
    float* sy2 = smf + HH * 128;
    int tid = threadIdx.x;
    int n_base = blockIdx.x * 128;

    for (int idx = tid; idx < HH * 32; idx += 256) {
        int k = idx >> 5, q = idx & 31;
        *(float4*)(sW + k*128 + q*4) = *(const float4*)(out_W + (size_t)k * VV + n_base + q*4);
    }
    for (int idx = tid; idx < BB * 64; idx += 256) {
        int bb = idx >> 6, q = idx & 63;
        float4 v = *(const float4*)(g_y2 + bb * HH + q*4);
        float* d = sy2 + bb*257 + q*4;
        d[0] = v.x; d[1] = v.y; d[2] = v.z; d[3] = v.w;
    }
    __syncthreads();

    int bg = tid >> 4, ng = tid & 15;
    int b0 = bg * 4, n0 = ng * 8;
    float acc[4][8];
    #pragma unroll
    for (int r = 0; r < 4; ++r)
        #pragma unroll
        for (int c = 0; c < 8; ++c) acc[r][c] = 0.f;
    for (int k = 0; k < HH; ++k) {
        float4 w0 = *(const float4*)(sW + k*128 + n0);
        float4 w1 = *(const float4*)(sW + k*128 + n0 + 4);
        float wv[8] = {w0.x, w0.y, w0.z, w0.w, w1.x, w1.y, w1.z, w1.w};
        #pragma unroll
        for (int r = 0; r < 4; ++r) {
            float yv = sy2[(b0+r)*257 + k];
            #pragma unroll
            for (int c = 0; c < 8; ++c) acc[r][c] += yv * wv[c];
        }
    }
    #pragma unroll
    for (int r = 0; r < 4; ++r)
        #pragma unroll
        for (int c = 0; c < 8; ++c)
            out[(size_t)(b0+r) * VV + n_base + n0 + c] = acc[r][c] + out_b[n_base + n0 + c];
}

// ---------------- launch ----------------
extern "C" void kernel_launch(void* const* d_in, const int* in_sizes, int n_in,
                              void* d_out, int out_size) {
    (void)in_sizes; (void)n_in; (void)out_size;
    const int*   seq     = (const int*)  d_in[0];
    const float* embed   = (const float*)d_in[1];
    const float* W1      = (const float*)d_in[2];
    const float* b1      = (const float*)d_in[3];
    const float* W2      = (const float*)d_in[4];
    const float* b2      = (const float*)d_in[5];
    const float* gamma   = (const float*)d_in[6];
    const float* beta_ln = (const float*)d_in[7];
    const float* rp_W    = (const float*)d_in[8];
    const float* rp_b    = (const float*)d_in[9];
    const float* out_W   = (const float*)d_in[10];
    const float* out_b   = (const float*)d_in[11];
    float* out = (float*)d_out;

    cudaFuncSetAttribute(k_ffn<1>, cudaFuncAttributeMaxDynamicSharedMemorySize, FFN_SMEM);
    cudaFuncSetAttribute(k_ffn<2>, cudaFuncAttributeMaxDynamicSharedMemorySize, FFN_SMEM);
    cudaFuncSetAttribute(k_scan,   cudaFuncAttributeMaxDynamicSharedMemorySize, SCAN_SMEM_BYTES);
    cudaFuncSetAttribute(k_out,    cudaFuncAttributeMaxDynamicSharedMemorySize, OUT_SMEM_BYTES);

    // 0. weight split + embedding gather/split
    k_prep<<<512, 256>>>(W1, W2);
    k_split<<<BB * LL * 64 / 256, 256>>>(seq, embed);
    // 1. ff = relu(A @ W1 + b1)   (HMMA, cp.async pipelined)
    k_ffn<1><<<dim3(4, BB*LL/128), 256, FFN_SMEM>>>(seq, embed, b1);
    // 2. x = ff @ W2 + b2 + e
    k_ffn<2><<<dim3(2, BB*LL/128), 256, FFN_SMEM>>>(seq, embed, b2);
    // 3. h = LayerNorm(x) in place
    k_ln<<<BB * LL / 8, 256>>>(gamma, beta_ln);
    // 4. chunked delta-rule scan
    k_scan<<<BB * 2, 256, SCAN_SMEM_BYTES>>>();
    // 5-7. readout
    k_read1<<<BB, 256>>>();
    k_read2<<<BB, HH>>>(rp_W, rp_b);
    k_out<<<VV / 128, 256, OUT_SMEM_BYTES>>>(out_W, out_b, out);
}

// round 6
// speedup vs baseline: 1.4211x; 1.4211x over previous
#include <cuda_runtime.h>
#include <cuda_fp16.h>
#include <math.h>
#include <stdint.h>

static constexpr int BB = 64;
static constexpr int LL = 2048;
static constexpr int HH = 256;
static constexpr int VV = 32000;
static constexpr int TT = LL - 1;
static constexpr float BETA = 0.9f;
static constexpr float OMB  = 0.1f;
static constexpr int CH = 32;

// ---------------- scratch ----------------
__device__ float  g_h [(size_t)BB*LL*HH];
__device__ __half g_af[(size_t)BB*LL*HH];       // gathered embed fp16
__device__ __half g_ff[(size_t)BB*LL*2*HH];     // relu(e@W1+b1) fp16
__device__ __half g_w1t[512*256];               // W1^T [n][k] fp16
__device__ __half g_w2t[256*512];               // W2^T [n][k] fp16
__device__ float  g_M [(size_t)BB*HH*HH];
__device__ float  g_y [BB*HH];
__device__ float  g_y2[BB*HH];

#define SWZ(o) ((o) ^ (((o) >> 3) & 0x70))

__device__ __forceinline__ uint32_t smem_u32(const void* p) {
    uint32_t a;
    asm("{ .reg .u64 t; cvta.to.shared.u64 t, %1; cvt.u32.u64 %0, t; }" : "=r"(a) : "l"(p));
    return a;
}
__device__ __forceinline__ uint32_t packh2(float a, float b) {
    __half2 t = __floats2half2_rn(a, b);
    return *reinterpret_cast<uint32_t*>(&t);
}
__device__ __forceinline__ void ldsm_x4(uint32_t* r, uint32_t addr) {
    asm volatile("ldmatrix.sync.aligned.m8n8.x4.shared.b16 {%0,%1,%2,%3}, [%4];"
        : "=r"(r[0]), "=r"(r[1]), "=r"(r[2]), "=r"(r[3]) : "r"(addr));
}
__device__ __forceinline__ void mma_f16(float* d, const uint32_t* a, uint32_t b0, uint32_t b1) {
    asm volatile("mma.sync.aligned.m16n8k16.row.col.f32.f16.f16.f32 "
        "{%0,%1,%2,%3}, {%4,%5,%6,%7}, {%8,%9}, {%0,%1,%2,%3};"
        : "+f"(d[0]), "+f"(d[1]), "+f"(d[2]), "+f"(d[3])
        : "r"(a[0]), "r"(a[1]), "r"(a[2]), "r"(a[3]), "r"(b0), "r"(b1));
}
__device__ __forceinline__ void cp16(uint32_t dst, const void* src) {
    asm volatile("cp.async.cg.shared.global [%0], [%1], 16;" :: "r"(dst), "l"(src));
}

// ---------------- 0a. weight transpose -> fp16 ----------------
__global__ void k_prep(const float* __restrict__ W1, const float* __restrict__ W2) {
    int idx = blockIdx.x * blockDim.x + threadIdx.x;   // 0..131071
    { int n = idx >> 8, k = idx & 255; g_w1t[idx] = __float2half_rn(W1[k * 512 + n]); }
    { int n = idx >> 9, k = idx & 511; g_w2t[idx] = __float2half_rn(W2[k * 256 + n]); }
}

// ---------------- 0b. embedding gather -> fp16 ----------------
__global__ void k_split(const int* __restrict__ seq, const float* __restrict__ embed) {
    size_t idx = (size_t)blockIdx.x * blockDim.x + threadIdx.x;   // B*L*64 quads
    int row = (int)(idx >> 6), q = (int)(idx & 63);
    int tok = seq[row];
    float4 v = ((const float4*)embed)[(size_t)tok * 64 + q];
    ((uint2*)g_af)[idx] = make_uint2(packh2(v.x, v.y), packh2(v.z, v.w));
}

// ---------------- 1+2. FFN GEMMs, fp16 HMMA + cp.async pipeline ----------------
// CTA tile 128x128, 8 warps (2m x 4n), warp 64x32, K chunk 64, stage 32KB x2.
static constexpr int FFN_SMEM = 1024 + 2 * 32768;   // 66560

__device__ __forceinline__ void ffn_compute(uint32_t aB, uint32_t bB,
                                            int wm, int wn, int lid, float (&acc)[4][4][4])
{
    #pragma unroll
    for (int ks = 0; ks < 4; ++ks) {
        uint32_t colA = ks * 32 + ((lid >> 4) << 4);
        uint32_t ah[4][4];
        #pragma unroll
        for (int mf = 0; mf < 4; ++mf) {
            uint32_t row = wm * 64 + mf * 16 + (lid & 15);
            ldsm_x4(ah[mf], aB + SWZ(row * 128 + colA));
        }
        uint32_t bh[2][4];
        #pragma unroll
        for (int nf = 0; nf < 2; ++nf) {
            uint32_t row = wn * 32 + nf * 16 + ((lid >> 4) << 3) + (lid & 7);
            uint32_t colB = ks * 32 + (((lid >> 3) & 1) << 4);
            ldsm_x4(bh[nf], bB + SWZ(row * 128 + colB));
        }
        #pragma unroll
        for (int mf = 0; mf < 4; ++mf)
            #pragma unroll
            for (int nf = 0; nf < 2; ++nf)
                #pragma unroll
                for (int j = 0; j < 2; ++j)
                    mma_f16(acc[mf][nf*2+j], ah[mf], bh[nf][j*2], bh[nf][j*2+1]);
    }
}

template<int PHASE>
__global__ __launch_bounds__(256, 2) void k_ffn(
    const int* __restrict__ seq, const float* __restrict__ embed,
    const float* __restrict__ bias)
{
    constexpr int K   = (PHASE == 1) ? HH : 2 * HH;
    constexpr int NC  = K / 64;
    constexpr int ARS = (PHASE == 1) ? HH : 2 * HH;

    extern __shared__ char sm[];
    int*   sseq  = (int*)sm;
    float* sbias = (float*)(sm + 512);
    char* st0 = sm + 1024;
    char* st1 = sm + 1024 + 32768;

    const int tid = threadIdx.x, wid = tid >> 5, lid = tid & 31;
    const int wm = wid & 1, wn = wid >> 1;
    const int m0  = blockIdx.y * 128;
    const int nb0 = blockIdx.x * 128;

    const __half* Af = (PHASE == 1) ? g_af  : g_ff;
    const __half* Wt = (PHASE == 1) ? g_w1t : g_w2t;

    if (tid < 128) {
        sbias[tid] = bias[nb0 + tid];
        if (PHASE == 2) sseq[tid] = seq[m0 + tid];
    }

    const int rr = tid >> 1, half = tid & 1;
    auto issue = [&](int c, char* st) {
        int k0 = c * 64;
        uint32_t aB = smem_u32(st), bB = aB + 16384;
        const char* asrc = (const char*)(Af + (size_t)(m0 + rr) * ARS + k0) + half * 64;
        const char* bsrc = (const char*)(Wt + (size_t)(nb0 + rr) * K + k0) + half * 64;
        #pragma unroll
        for (int j = 0; j < 4; ++j) {
            uint32_t off = SWZ((uint32_t)(rr * 128 + half * 64 + j * 16));
            cp16(aB + off, asrc + j * 16);
            cp16(bB + off, bsrc + j * 16);
        }
        asm volatile("cp.async.commit_group;" ::: "memory");
    };

    float acc[4][4][4];
    #pragma unroll
    for (int a = 0; a < 4; ++a)
        #pragma unroll
        for (int b = 0; b < 4; ++b)
            #pragma unroll
            for (int c = 0; c < 4; ++c) acc[a][b][c] = 0.f;

    issue(0, st0);
    for (int c = 0; c < NC; ++c) {
        char* cur = (c & 1) ? st1 : st0;
        if (c + 1 < NC) {
            issue(c + 1, ((c + 1) & 1) ? st1 : st0);
            asm volatile("cp.async.wait_group 1;" ::: "memory");
        } else {
            asm volatile("cp.async.wait_group 0;" ::: "memory");
        }
        __syncthreads();
        uint32_t aB = smem_u32(cur);
        ffn_compute(aB, aB + 16384, wm, wn, lid, acc);
        __syncthreads();
    }

    // ---- epilogue ----
    const int qm = lid >> 2, qn = (lid & 3) * 2;
    if (PHASE == 1) {
        uint32_t* SH = (uint32_t*)(sm + 1024);   // [128][64] half2
        #pragma unroll
        for (int mf = 0; mf < 4; ++mf)
            #pragma unroll
            for (int nf = 0; nf < 2; ++nf)
                #pragma unroll
                for (int j = 0; j < 2; ++j) {
                    const float* d = acc[mf][nf*2+j];
                    int nl = wn * 32 + nf * 16 + j * 8 + qn;
                    #pragma unroll
                    for (int hh = 0; hh < 2; ++hh) {
                        int ml = wm * 64 + mf * 16 + qm + hh * 8;
                        float v0 = fmaxf(d[hh*2+0] + sbias[nl],   0.f);
                        float v1 = fmaxf(d[hh*2+1] + sbias[nl+1], 0.f);
                        SH[ml * 64 + (nl >> 1)] = packh2(v0, v1);
                    }
                }
        __syncthreads();
        int row = tid >> 1, part = tid & 1;
        uint4* gh = (uint4*)(g_ff + (size_t)(m0 + row) * 512 + nb0);
        const uint4* shp = (const uint4*)SH;
        #pragma unroll
        for (int j = 0; j < 8; ++j) {
            int q = part * 8 + j;
            gh[q] = shp[row * 16 + q];
        }
    } else {
        float* SF = (float*)(sm + 1024);         // [128][128] f32
        #pragma unroll
        for (int mf = 0; mf < 4; ++mf)
            #pragma unroll
            for (int nf = 0; nf < 2; ++nf)
                #pragma unroll
                for (int j = 0; j < 2; ++j) {
                    const float* d = acc[mf][nf*2+j];
                    int nl = wn * 32 + nf * 16 + j * 8 + qn;
                    #pragma unroll
                    for (int hh = 0; hh < 2; ++hh) {
                        int ml = wm * 64 + mf * 16 + qm + hh * 8;
                        SF[ml * 128 + nl]     = d[hh*2+0] + sbias[nl];
                        SF[ml * 128 + nl + 1] = d[hh*2+1] + sbias[nl+1];
                    }
                }
        __syncthreads();
        int row = tid >> 1, part = tid & 1;
        int tok = sseq[row];
        const float4* ep = (const float4*)(embed + (size_t)tok * HH + nb0);
        const float4* sfp = (const float4*)(SF + row * 128);
        float4* gp = (float4*)(g_h + (size_t)(m0 + row) * HH + nb0);
        #pragma unroll
        for (int j = 0; j < 16; ++j) {
            int c4 = part * 16 + j;
            float4 f = sfp[c4];
            float4 e = ep[c4];
            f.x += e.x; f.y += e.y; f.z += e.z; f.w += e.w;
            gp[c4] = f;
        }
    }
}

// ---------------- 3. LayerNorm: one warp per row ----------------
__global__ void k_ln(const float* __restrict__ gamma, const float* __restrict__ beta_ln) {
    int warp = threadIdx.x >> 5, lane = threadIdx.x & 31;
    size_t row = (size_t)blockIdx.x * 8 + warp;
    float4* xp = (float4*)(g_h + row * HH);
    float4 a = xp[lane * 2];
    float4 b = xp[lane * 2 + 1];
    float s = a.x + a.y + a.z + a.w + b.x + b.y + b.z + b.w;
    #pragma unroll
    for (int o = 16; o; o >>= 1) s += __shfl_xor_sync(0xffffffffu, s, o);
    float mu = s * (1.0f / HH);
    float dx[8] = {a.x-mu, a.y-mu, a.z-mu, a.w-mu, b.x-mu, b.y-mu, b.z-mu, b.w-mu};
    float v = 0.f;
    #pragma unroll
    for (int q = 0; q < 8; ++q) v += dx[q] * dx[q];
    #pragma unroll
    for (int o = 16; o; o >>= 1) v += __shfl_xor_sync(0xffffffffu, v, o);
    float inv = rsqrtf(v * (1.0f / HH) + 1e-5f);
    float4 g0 = ((const float4*)gamma)[lane * 2];
    float4 g1 = ((const float4*)gamma)[lane * 2 + 1];
    float4 t0 = ((const float4*)beta_ln)[lane * 2];
    float4 t1 = ((const float4*)beta_ln)[lane * 2 + 1];
    float4 o0, o1;
    o0.x = dx[0]*inv*g0.x + t0.x; o0.y = dx[1]*inv*g0.y + t0.y;
    o0.z = dx[2]*inv*g0.z + t0.z; o0.w = dx[3]*inv*g0.w + t0.w;
    o1.x = dx[4]*inv*g1.x + t1.x; o1.y = dx[5]*inv*g1.y + t1.y;
    o1.z = dx[6]*inv*g1.z + t1.z; o1.w = dx[7]*inv*g1.w + t1.w;
    xp[lane * 2]     = o0;
    xp[lane * 2 + 1] = o1;
}

// ---------------- 4. chunked momentum delta-rule scan ----------------
static constexpr int SCAN_SMEM_FLOATS = 128*257 + CH*257 + CH*128 + CH*CH + CH + 40 + 544;
static constexpr int SCAN_SMEM_BYTES  = SCAN_SMEM_FLOATS * 4;

__global__ __launch_bounds__(256, 1) void k_scan() {
    extern __shared__ float smf[];
    float* sM  = smf;
    float* sK  = sM + 128*257;
    float* sD  = sK + CH*257;
    float* sA  = sD + CH*128;
    float* sc  = sA + CH*CH;
    float* spw = sc + CH;
    int*   sPT = (int*)(spw + CH + 8);   // 528 packed (t<<8|s)

    int tid = threadIdx.x;
    int b   = blockIdx.x >> 1;
    int r0  = (blockIdx.x & 1) * 128;

    for (int i = tid; i < 128*257; i += 256) sM[i] = 0.f;
    if (tid == 0) {
        spw[0] = 1.f;
        for (int i = 1; i <= CH; ++i) spw[i] = spw[i-1] * BETA;
    }
    // pair table (computed once)
    for (int p = tid; p < 528; p += 256) {
        int t = (int)((sqrtf(8.f * p + 1.f) - 1.f) * 0.5f);
        while ((t + 1) * (t + 2) / 2 <= p) ++t;
        while (t * (t + 1) / 2 > p) --t;
        int s = p - t * (t + 1) / 2;
        sPT[p] = (t << 8) | s;
    }
    __syncthreads();

    const int u_ig = tid >> 3;
    const int u_tg = tid & 7;
    const int m_ig = tid & 15;
    const int m_jg = tid >> 4;

    const float* hb = g_h + (size_t)b * LL * HH;

    for (int t0 = 0; t0 < TT; t0 += CH) {
        int Cc = min(CH, TT - t0);
        __syncthreads();

        for (int idx = tid; idx < Cc * 64; idx += 256) {
            int lt = idx >> 6, q = idx & 63;
            float4 v = *(const float4*)(hb + (size_t)(t0 + lt) * HH + q * 4);
            float* dst = sK + lt*257 + q*4;
            dst[0] = v.x; dst[1] = v.y; dst[2] = v.z; dst[3] = v.w;
        }
        __syncthreads();

        int P = Cc * (Cc + 1) / 2;
        for (int p = tid; p < P; p += 256) {
            int pr = sPT[p];
            int t = pr >> 8, s = pr & 255;
            const float* kt = sK + t*257;
            const float* ks = sK + s*257;
            float dot = 0.f;
            #pragma unroll 8
            for (int j = 0; j < HH; ++j) dot += kt[j] * ks[j];
            if (s == t) sc[t] = dot;
            else        sA[t*CH + s] = dot;
        }
        __syncthreads();
        if (tid < Cc) sc[tid] = 1.0f / (sc[tid] + 1e-6f);
        __syncthreads();
        for (int p = tid; p < P; p += 256) {
            int pr = sPT[p];
            int t = pr >> 8, s = pr & 255;
            if (s < t) sA[t*CH + s] *= sc[t] * OMB * spw[t - 1 - s];
        }
        __syncthreads();

        // ---- U = K * M^T, fold into rhs -> sD ----
        {
            int i0 = u_ig * 4, lt0 = u_tg * 4;
            float acc[4][4];
            #pragma unroll
            for (int r = 0; r < 4; ++r)
                #pragma unroll
                for (int c = 0; c < 4; ++c) acc[r][c] = 0.f;
            #pragma unroll 4
            for (int j = 0; j < HH; ++j) {
                float a0 = sM[(i0+0)*257 + j], a1 = sM[(i0+1)*257 + j];
                float a2 = sM[(i0+2)*257 + j], a3 = sM[(i0+3)*257 + j];
                float b0 = sK[(lt0+0)*257 + j], b1 = sK[(lt0+1)*257 + j];
                float b2 = sK[(lt0+2)*257 + j], b3 = sK[(lt0+3)*257 + j];
                acc[0][0] += a0*b0; acc[0][1] += a0*b1; acc[0][2] += a0*b2; acc[0][3] += a0*b3;
                acc[1][0] += a1*b0; acc[1][1] += a1*b1; acc[1][2] += a1*b2; acc[1][3] += a1*b3;
                acc[2][0] += a2*b0; acc[2][1] += a2*b1; acc[2][2] += a2*b2; acc[2][3] += a2*b3;
                acc[3][0] += a3*b0; acc[3][1] += a3*b1; acc[3][2] += a3*b2; acc[3][3] += a3*b3;
            }
            #pragma unroll
            for (int c = 0; c < 4; ++c) {
                int lt = lt0 + c;
                if (lt < Cc) {
                    float coef = sc[lt] * spw[lt];
                    #pragma unroll
                    for (int r = 0; r < 4; ++r) {
                        int i = i0 + r;
                        sD[lt*128 + i] = sK[lt*257 + r0 + i] - coef * acc[r][c];
                    }
                }
            }
        }
        __syncthreads();

        // ---- forward substitution: register triangular solve, no barriers ----
        if (tid < 128) {
            float d[CH];
            #pragma unroll
            for (int t = 0; t < CH; ++t) d[t] = sD[t*128 + tid];
            #pragma unroll
            for (int s = 0; s < CH - 1; ++s)
                #pragma unroll
                for (int t = s + 1; t < CH; ++t)
                    d[t] -= sA[t*CH + s] * d[s];
            #pragma unroll
            for (int t = 0; t < CH; ++t)
                if (t < Cc) sD[t*128 + tid] = d[t];
        }
        __syncthreads();

        // ---- rank-Cc M update ----
        {
            float bc = spw[Cc];
            int i0 = m_ig * 8, j0 = m_jg * 16;
            float acc[8][16];
            #pragma unroll
            for (int r = 0; r < 8; ++r)
                #pragma unroll
                for (int c = 0; c < 16; ++c)
                    acc[r][c] = sM[(i0+r)*257 + j0 + c] * bc;
            for (int s = 0; s < Cc; ++s) {
                float w = OMB * spw[Cc - 1 - s];
                float4 d0 = *(const float4*)(sD + s*128 + i0);
                float4 d1 = *(const float4*)(sD + s*128 + i0 + 4);
                float dr[8] = {d0.x*w, d0.y*w, d0.z*w, d0.w*w,
                               d1.x*w, d1.y*w, d1.z*w, d1.w*w};
                #pragma unroll
                for (int c = 0; c < 16; ++c) {
                    float kv = sK[s*257 + j0 + c];
                    #pragma unroll
                    for (int r = 0; r < 8; ++r) acc[r][c] += dr[r] * kv;
                }
            }
            #pragma unroll
            for (int r = 0; r < 8; ++r)
                #pragma unroll
                for (int c = 0; c < 16; ++c)
                    sM[(i0+r)*257 + j0 + c] = acc[r][c];
        }
    }

    __syncthreads();
    for (int idx = tid; idx < 128 * HH; idx += 256) {
        int i = idx >> 8, j = idx & 255;
        g_M[((size_t)b * HH + r0 + i) * HH + j] = sM[i*257 + j];
    }
}

// ---------------- 5-7. readout ----------------
__global__ void k_read1() {
    int b = blockIdx.x;
    int tid = threadIdx.x;
    __shared__ float hl[HH];
    hl[tid] = g_h[((size_t)b * LL + (LL - 1)) * HH + tid];
    __syncthreads();
    int w = tid >> 5, lane = tid & 31;
    for (int i = w; i < HH; i += 8) {
        const float* Mr = g_M + ((size_t)b * HH + i) * HH;
        float s = 0.f;
        #pragma unroll
        for (int j = lane; j < HH; j += 32) s += Mr[j] * hl[j];
        #pragma unroll
        for (int o = 16; o; o >>= 1) s += __shfl_xor_sync(0xffffffffu, s, o);
        if (lane == 0) g_y[b * HH + i] = s;
    }
}

__global__ void k_read2(const float* __restrict__ rp_W, const float* __restrict__ rp_b) {
    int b = blockIdx.x, n = threadIdx.x;
    __shared__ float ys[HH];
    ys[n] = g_y[b * HH + n];
    __syncthreads();
    float acc = rp_b[n];
    #pragma unroll 4
    for (int k = 0; k < HH; ++k) acc += ys[k] * rp_W[k * HH + n];
    g_y2[b * HH + n] = acc;
}

static constexpr int OUT_SMEM_BYTES = (HH * 128 + BB * 257) * 4;

__global__ __launch_bounds__(256) void k_out(
    const float* __restrict__ out_W, const float* __restrict__ out_b,
    float* __restrict__ out)
{
    extern __shared__ float smf[];
    float* sW  = smf;
    float* sy2 = smf + HH * 128;
    int tid = threadIdx.x;
    int n_base = blockIdx.x * 128;

    for (int idx = tid; idx < HH * 32; idx += 256) {
        int k = idx >> 5, q = idx & 31;
        *(float4*)(sW + k*128 + q*4) = *(const float4*)(out_W + (size_t)k * VV + n_base + q*4);
    }
    for (int idx = tid; idx < BB * 64; idx += 256) {
        int bb = idx >> 6, q = idx & 63;
        float4 v = *(const float4*)(g_y2 + bb * HH + q*4);
        float* d = sy2 + bb*257 + q*4;
        d[0] = v.x; d[1] = v.y; d[2] = v.z; d[3] = v.w;
    }
    __syncthreads();

    int bg = tid >> 4, ng = tid & 15;
    int b0 = bg * 4, n0 = ng * 8;
    float acc[4][8];
    #pragma unroll
    for (int r = 0; r < 4; ++r)
        #pragma unroll
        for (int c = 0; c < 8; ++c) acc[r][c] = 0.f;
    for (int k = 0; k < HH; ++k) {
        float4 w0 = *(const float4*)(sW + k*128 + n0);
        float4 w1 = *(const float4*)(sW + k*128 + n0 + 4);
        float wv[8] = {w0.x, w0.y, w0.z, w0.w, w1.x, w1.y, w1.z, w1.w};
        #pragma unroll
        for (int r = 0; r < 4; ++r) {
            float yv = sy2[(b0+r)*257 + k];
            #pragma unroll
            for (int c = 0; c < 8; ++c) acc[r][c] += yv * wv[c];
        }
    }
    #pragma unroll
    for (int r = 0; r < 4; ++r)
        #pragma unroll
        for (int c = 0; c < 8; ++c)
            out[(size_t)(b0+r) * VV + n_base + n0 + c] = acc[r][c] + out_b[n_base + n0 + c];
}

// ---------------- launch ----------------
extern "C" void kernel_launch(void* const* d_in, const int* in_sizes, int n_in,
                              void* d_out, int out_size) {
    (void)in_sizes; (void)n_in; (void)out_size;
    const int*   seq     = (const int*)  d_in[0];
    const float* embed   = (const float*)d_in[1];
    const float* W1      = (const float*)d_in[2];
    const float* b1      = (const float*)d_in[3];
    const float* W2      = (const float*)d_in[4];
    const float* b2      = (const float*)d_in[5];
    const float* gamma   = (const float*)d_in[6];
    const float* beta_ln = (const float*)d_in[7];
    const float* rp_W    = (const float*)d_in[8];
    const float* rp_b    = (const float*)d_in[9];
    const float* out_W   = (const float*)d_in[10];
    const float* out_b   = (const float*)d_in[11];
    float* out = (float*)d_out;

    cudaFuncSetAttribute(k_ffn<1>, cudaFuncAttributeMaxDynamicSharedMemorySize, FFN_SMEM);
    cudaFuncSetAttribute(k_ffn<2>, cudaFuncAttributeMaxDynamicSharedMemorySize, FFN_SMEM);
    cudaFuncSetAttribute(k_scan,   cudaFuncAttributeMaxDynamicSharedMemorySize, SCAN_SMEM_BYTES);
    cudaFuncSetAttribute(k_out,    cudaFuncAttributeMaxDynamicSharedMemorySize, OUT_SMEM_BYTES);

    k_prep<<<512, 256>>>(W1, W2);
    k_split<<<BB * LL * 64 / 256, 256>>>(seq, embed);
    k_ffn<1><<<dim3(4, BB*LL/128), 256, FFN_SMEM>>>(seq, embed, b1);
    k_ffn<2><<<dim3(2, BB*LL/128), 256, FFN_SMEM>>>(seq, embed, b2);
    k_ln<<<BB * LL / 8, 256>>>(gamma, beta_ln);
    k_scan<<<BB * 2, 256, SCAN_SMEM_BYTES>>>();
    k_read1<<<BB, 256>>>();
    k_read2<<<BB, HH>>>(rp_W, rp_b);
    k_out<<<VV / 128, 256, OUT_SMEM_BYTES>>>(out_W, out_b, out);
}

// round 8
// speedup vs baseline: 2.5090x; 1.7656x over previous
#include <cuda_runtime.h>
#include <cuda_fp16.h>
#include <cuda_bf16.h>
#include <math.h>
#include <stdint.h>

static constexpr int BB = 64;
static constexpr int LL = 2048;
static constexpr int HH = 256;
static constexpr int VV = 32000;
static constexpr int TT = LL - 1;
static constexpr float BETA = 0.9f;
static constexpr float OMB  = 0.1f;
static constexpr int CH = 32;

// ---------------- scratch ----------------
__device__ float  g_h [(size_t)BB*LL*HH];
__device__ __half g_af[(size_t)BB*LL*HH];
__device__ __half g_ff[(size_t)BB*LL*2*HH];
__device__ __half g_w1t[512*256];
__device__ __half g_w2t[256*512];
__device__ float  g_M [(size_t)BB*HH*HH];
__device__ float  g_y [BB*HH];
__device__ float  g_y2[BB*HH];

#define SWZ(o)  ((o) ^ (((o) >> 3) & 0x70))   // 128B rows
#define SWZ5(o) ((o) ^ (((o) >> 5) & 0x70))   // 512B rows

__device__ __forceinline__ uint32_t smem_u32(const void* p) {
    uint32_t a;
    asm("{ .reg .u64 t; cvta.to.shared.u64 t, %1; cvt.u32.u64 %0, t; }" : "=r"(a) : "l"(p));
    return a;
}
__device__ __forceinline__ uint32_t packh2(float a, float b) {
    __half2 t = __floats2half2_rn(a, b);
    return *reinterpret_cast<uint32_t*>(&t);
}
__device__ __forceinline__ uint32_t packb2f(float a, float b) {
    __nv_bfloat162 t = __floats2bfloat162_rn(a, b);
    return *reinterpret_cast<uint32_t*>(&t);
}
__device__ __forceinline__ float bfu(uint16_t h) {
    return __uint_as_float(((uint32_t)h) << 16);
}
__device__ __forceinline__ void ldsm_x4(uint32_t* r, uint32_t addr) {
    asm volatile("ldmatrix.sync.aligned.m8n8.x4.shared.b16 {%0,%1,%2,%3}, [%4];"
        : "=r"(r[0]), "=r"(r[1]), "=r"(r[2]), "=r"(r[3]) : "r"(addr));
}
__device__ __forceinline__ void ldsm_x4t(uint32_t* r, uint32_t addr) {
    asm volatile("ldmatrix.sync.aligned.m8n8.x4.trans.shared.b16 {%0,%1,%2,%3}, [%4];"
        : "=r"(r[0]), "=r"(r[1]), "=r"(r[2]), "=r"(r[3]) : "r"(addr));
}
__device__ __forceinline__ void ldsm_x2(uint32_t* r, uint32_t addr) {
    asm volatile("ldmatrix.sync.aligned.m8n8.x2.shared.b16 {%0,%1}, [%2];"
        : "=r"(r[0]), "=r"(r[1]) : "r"(addr));
}
__device__ __forceinline__ void mma_f16(float* d, const uint32_t* a, uint32_t b0, uint32_t b1) {
    asm volatile("mma.sync.aligned.m16n8k16.row.col.f32.f16.f16.f32 "
        "{%0,%1,%2,%3}, {%4,%5,%6,%7}, {%8,%9}, {%0,%1,%2,%3};"
        : "+f"(d[0]), "+f"(d[1]), "+f"(d[2]), "+f"(d[3])
        : "r"(a[0]), "r"(a[1]), "r"(a[2]), "r"(a[3]), "r"(b0), "r"(b1));
}
__device__ __forceinline__ void mma_bf(float* d, const uint32_t* a, uint32_t b0, uint32_t b1) {
    asm volatile("mma.sync.aligned.m16n8k16.row.col.f32.bf16.bf16.f32 "
        "{%0,%1,%2,%3}, {%4,%5,%6,%7}, {%8,%9}, {%0,%1,%2,%3};"
        : "+f"(d[0]), "+f"(d[1]), "+f"(d[2]), "+f"(d[3])
        : "r"(a[0]), "r"(a[1]), "r"(a[2]), "r"(a[3]), "r"(b0), "r"(b1));
}
__device__ __forceinline__ void cp16(uint32_t dst, const void* src) {
    asm volatile("cp.async.cg.shared.global [%0], [%1], 16;" :: "r"(dst), "l"(src));
}

// ---------------- 0a/0b. prep ----------------
__global__ void k_prep(const float* __restrict__ W1, const float* __restrict__ W2) {
    int idx = blockIdx.x * blockDim.x + threadIdx.x;
    { int n = idx >> 8, k = idx & 255; g_w1t[idx] = __float2half_rn(W1[k * 512 + n]); }
    { int n = idx >> 9, k = idx & 511; g_w2t[idx] = __float2half_rn(W2[k * 256 + n]); }
}
__global__ void k_split(const int* __restrict__ seq, const float* __restrict__ embed) {
    size_t idx = (size_t)blockIdx.x * blockDim.x + threadIdx.x;
    int row = (int)(idx >> 6), q = (int)(idx & 63);
    int tok = seq[row];
    float4 v = ((const float4*)embed)[(size_t)tok * 64 + q];
    ((uint2*)g_af)[idx] = make_uint2(packh2(v.x, v.y), packh2(v.z, v.w));
}

// ---------------- 1+2. FFN (unchanged from round 6) ----------------
static constexpr int FFN_SMEM = 1024 + 2 * 32768;

__device__ __forceinline__ void ffn_compute(uint32_t aB, uint32_t bB,
                                            int wm, int wn, int lid, float (&acc)[4][4][4])
{
    #pragma unroll
    for (int ks = 0; ks < 4; ++ks) {
        uint32_t colA = ks * 32 + ((lid >> 4) << 4);
        uint32_t ah[4][4];
        #pragma unroll
        for (int mf = 0; mf < 4; ++mf) {
            uint32_t row = wm * 64 + mf * 16 + (lid & 15);
            ldsm_x4(ah[mf], aB + SWZ(row * 128 + colA));
        }
        uint32_t bh[2][4];
        #pragma unroll
        for (int nf = 0; nf < 2; ++nf) {
            uint32_t row = wn * 32 + nf * 16 + ((lid >> 4) << 3) + (lid & 7);
            uint32_t colB = ks * 32 + (((lid >> 3) & 1) << 4);
            ldsm_x4(bh[nf], bB + SWZ(row * 128 + colB));
        }
        #pragma unroll
        for (int mf = 0; mf < 4; ++mf)
            #pragma unroll
            for (int nf = 0; nf < 2; ++nf)
                #pragma unroll
                for (int j = 0; j < 2; ++j)
                    mma_f16(acc[mf][nf*2+j], ah[mf], bh[nf][j*2], bh[nf][j*2+1]);
    }
}

template<int PHASE>
__global__ __launch_bounds__(256, 2) void k_ffn(
    const int* __restrict__ seq, const float* __restrict__ embed,
    const float* __restrict__ bias)
{
    constexpr int K   = (PHASE == 1) ? HH : 2 * HH;
    constexpr int NC  = K / 64;
    constexpr int ARS = (PHASE == 1) ? HH : 2 * HH;

    extern __shared__ char sm[];
    int*   sseq  = (int*)sm;
    float* sbias = (float*)(sm + 512);
    char* st0 = sm + 1024;
    char* st1 = sm + 1024 + 32768;

    const int tid = threadIdx.x, wid = tid >> 5, lid = tid & 31;
    const int wm = wid & 1, wn = wid >> 1;
    const int m0  = blockIdx.y * 128;
    const int nb0 = blockIdx.x * 128;

    const __half* Af = (PHASE == 1) ? g_af  : g_ff;
    const __half* Wt = (PHASE == 1) ? g_w1t : g_w2t;

    if (tid < 128) {
        sbias[tid] = bias[nb0 + tid];
        if (PHASE == 2) sseq[tid] = seq[m0 + tid];
    }

    const int rr = tid >> 1, half = tid & 1;
    auto issue = [&](int c, char* st) {
        int k0 = c * 64;
        uint32_t aB = smem_u32(st), bB = aB + 16384;
        const char* asrc = (const char*)(Af + (size_t)(m0 + rr) * ARS + k0) + half * 64;
        const char* bsrc = (const char*)(Wt + (size_t)(nb0 + rr) * K + k0) + half * 64;
        #pragma unroll
        for (int j = 0; j < 4; ++j) {
            uint32_t off = SWZ((uint32_t)(rr * 128 + half * 64 + j * 16));
            cp16(aB + off, asrc + j * 16);
            cp16(bB + off, bsrc + j * 16);
        }
        asm volatile("cp.async.commit_group;" ::: "memory");
    };

    float acc[4][4][4];
    #pragma unroll
    for (int a = 0; a < 4; ++a)
        #pragma unroll
        for (int b = 0; b < 4; ++b)
            #pragma unroll
            for (int c = 0; c < 4; ++c) acc[a][b][c] = 0.f;

    issue(0, st0);
    for (int c = 0; c < NC; ++c) {
        char* cur = (c & 1) ? st1 : st0;
        if (c + 1 < NC) {
            issue(c + 1, ((c + 1) & 1) ? st1 : st0);
            asm volatile("cp.async.wait_group 1;" ::: "memory");
        } else {
            asm volatile("cp.async.wait_group 0;" ::: "memory");
        }
        __syncthreads();
        uint32_t aB = smem_u32(cur);
        ffn_compute(aB, aB + 16384, wm, wn, lid, acc);
        __syncthreads();
    }

    const int qm = lid >> 2, qn = (lid & 3) * 2;
    if (PHASE == 1) {
        uint32_t* SH = (uint32_t*)(sm + 1024);
        #pragma unroll
        for (int mf = 0; mf < 4; ++mf)
            #pragma unroll
            for (int nf = 0; nf < 2; ++nf)
                #pragma unroll
                for (int j = 0; j < 2; ++j) {
                    const float* d = acc[mf][nf*2+j];
                    int nl = wn * 32 + nf * 16 + j * 8 + qn;
                    #pragma unroll
                    for (int hh = 0; hh < 2; ++hh) {
                        int ml = wm * 64 + mf * 16 + qm + hh * 8;
                        float v0 = fmaxf(d[hh*2+0] + sbias[nl],   0.f);
                        float v1 = fmaxf(d[hh*2+1] + sbias[nl+1], 0.f);
                        SH[ml * 64 + (nl >> 1)] = packh2(v0, v1);
                    }
                }
        __syncthreads();
        int row = tid >> 1, part = tid & 1;
        uint4* gh = (uint4*)(g_ff + (size_t)(m0 + row) * 512 + nb0);
        const uint4* shp = (const uint4*)SH;
        #pragma unroll
        for (int j = 0; j < 8; ++j) {
            int q = part * 8 + j;
            gh[q] = shp[row * 16 + q];
        }
    } else {
        float* SF = (float*)(sm + 1024);
        #pragma unroll
        for (int mf = 0; mf < 4; ++mf)
            #pragma unroll
            for (int nf = 0; nf < 2; ++nf)
                #pragma unroll
                for (int j = 0; j < 2; ++j) {
                    const float* d = acc[mf][nf*2+j];
                    int nl = wn * 32 + nf * 16 + j * 8 + qn;
                    #pragma unroll
                    for (int hh = 0; hh < 2; ++hh) {
                        int ml = wm * 64 + mf * 16 + qm + hh * 8;
                        SF[ml * 128 + nl]     = d[hh*2+0] + sbias[nl];
                        SF[ml * 128 + nl + 1] = d[hh*2+1] + sbias[nl+1];
                    }
                }
        __syncthreads();
        int row = tid >> 1, part = tid & 1;
        int tok = sseq[row];
        const float4* ep = (const float4*)(embed + (size_t)tok * HH + nb0);
        const float4* sfp = (const float4*)(SF + row * 128);
        float4* gp = (float4*)(g_h + (size_t)(m0 + row) * HH + nb0);
        #pragma unroll
        for (int j = 0; j < 16; ++j) {
            int c4 = part * 16 + j;
            float4 f = sfp[c4];
            float4 e = ep[c4];
            f.x += e.x; f.y += e.y; f.z += e.z; f.w += e.w;
            gp[c4] = f;
        }
    }
}

// ---------------- 3. LayerNorm (unchanged) ----------------
__global__ void k_ln(const float* __restrict__ gamma, const float* __restrict__ beta_ln) {
    int warp = threadIdx.x >> 5, lane = threadIdx.x & 31;
    size_t row = (size_t)blockIdx.x * 8 + warp;
    float4* xp = (float4*)(g_h + row * HH);
    float4 a = xp[lane * 2];
    float4 b = xp[lane * 2 + 1];
    float s = a.x + a.y + a.z + a.w + b.x + b.y + b.z + b.w;
    #pragma unroll
    for (int o = 16; o; o >>= 1) s += __shfl_xor_sync(0xffffffffu, s, o);
    float mu = s * (1.0f / HH);
    float dx[8] = {a.x-mu, a.y-mu, a.z-mu, a.w-mu, b.x-mu, b.y-mu, b.z-mu, b.w-mu};
    float v = 0.f;
    #pragma unroll
    for (int q = 0; q < 8; ++q) v += dx[q] * dx[q];
    #pragma unroll
    for (int o = 16; o; o >>= 1) v += __shfl_xor_sync(0xffffffffu, v, o);
    float inv = rsqrtf(v * (1.0f / HH) + 1e-5f);
    float4 g0 = ((const float4*)gamma)[lane * 2];
    float4 g1 = ((const float4*)gamma)[lane * 2 + 1];
    float4 t0 = ((const float4*)beta_ln)[lane * 2];
    float4 t1 = ((const float4*)beta_ln)[lane * 2 + 1];
    float4 o0, o1;
    o0.x = dx[0]*inv*g0.x + t0.x; o0.y = dx[1]*inv*g0.y + t0.y;
    o0.z = dx[2]*inv*g0.z + t0.z; o0.w = dx[3]*inv*g0.w + t0.w;
    o1.x = dx[4]*inv*g1.x + t1.x; o1.y = dx[5]*inv*g1.y + t1.y;
    o1.z = dx[6]*inv*g1.z + t1.z; o1.w = dx[7]*inv*g1.w + t1.w;
    xp[lane * 2]     = o0;
    xp[lane * 2 + 1] = o1;
}

// ---------------- 4. scan: HMMA chunked delta rule ----------------
// CTA (b, half) owns M rows r0..r0+127 as fp32 mma accumulators (warp w: rows 16w..16w+15).
// Per chunk: K->bf16 hi/lo smem; Gram + U via bf16 split-2 3-term mma; scalar coefs;
// register triangular solve; M update via mma with ldmatrix.trans on K.
static constexpr uint32_t OFF_MH  = 0;        // [128][512B] bf16 swz5
static constexpr uint32_t OFF_ML  = 65536;
static constexpr uint32_t OFF_KH  = 131072;   // [32][512B]
static constexpr uint32_t OFF_KL  = 147456;
static constexpr uint32_t OFF_SD  = 163840;   // [32][128] f32 raw U
static constexpr uint32_t OFF_DTH = 180224;   // [128][80B] bf16
static constexpr uint32_t OFF_DTL = 190464;
static constexpr uint32_t OFF_G   = 200704;   // [32][36] f32
static constexpr uint32_t OFF_A   = 205312;   // [32][32] f32
static constexpr uint32_t OFF_SC  = 209408;   // sc[32], ct[32], wv[32], spw[33]
static constexpr int SCAN_SMEM_BYTES = 210048;

__global__ __launch_bounds__(256, 1) void k_scan() {
    extern __shared__ char smc[];
    const uint32_t sb = smem_u32(smc);
    const uint32_t MH = sb + OFF_MH, ML = sb + OFF_ML;
    const uint32_t KH = sb + OFF_KH, KL = sb + OFF_KL;
    float* sD  = (float*)(smc + OFF_SD);
    float* sG  = (float*)(smc + OFF_G);
    float* sA  = (float*)(smc + OFF_A);
    float* sc  = (float*)(smc + OFF_SC);
    float* ct  = sc + 32;
    float* wv  = ct + 32;
    float* spw = wv + 32;

    const int tid = threadIdx.x, wid = tid >> 5, lid = tid & 31;
    const int qm = lid >> 2, qn = (lid & 3) * 2;
    const int b  = blockIdx.x >> 1;
    const int r0 = (blockIdx.x & 1) * 128;
    const float* hb = g_h + (size_t)b * LL * HH;

    // zero sM (bf16 hi/lo), spw table
    for (int i = tid; i < 131072 / 16; i += 256)
        ((uint4*)(smc + OFF_MH))[i] = make_uint4(0, 0, 0, 0);
    if (tid == 0) {
        spw[0] = 1.f;
        for (int i = 1; i <= CH; ++i) spw[i] = spw[i-1] * BETA;
    }
    __syncthreads();

    float acc[32][4];   // M rows 16*wid + {qm, qm+8}, cols nf*8 + {qn, qn+1}
    #pragma unroll
    for (int f = 0; f < 32; ++f)
        #pragma unroll
        for (int q = 0; q < 4; ++q) acc[f][q] = 0.f;

    const int klt = tid >> 3, kq = tid & 7;   // K-load mapping

    for (int t0 = 0; t0 < TT; t0 += CH) {
        const int Cc = min(CH, TT - t0);
        __syncthreads();

        // ---- (a) load K chunk -> bf16 hi/lo swz5 ----
        {
            const float* src = hb + (size_t)(t0 + klt) * HH + kq * 32;
            bool pad = (klt >= Cc);
            #pragma unroll
            for (int g = 0; g < 4; ++g) {
                float f[8];
                if (pad) {
                    #pragma unroll
                    for (int q = 0; q < 8; ++q) f[q] = 0.f;
                } else {
                    float4 v0 = *(const float4*)(src + g*8);
                    float4 v1 = *(const float4*)(src + g*8 + 4);
                    f[0]=v0.x; f[1]=v0.y; f[2]=v0.z; f[3]=v0.w;
                    f[4]=v1.x; f[5]=v1.y; f[6]=v1.z; f[7]=v1.w;
                }
                uint32_t hw[4], lw[4];
                #pragma unroll
                for (int q = 0; q < 4; ++q) {
                    __nv_bfloat16 h0 = __float2bfloat16(f[2*q]);
                    __nv_bfloat16 h1 = __float2bfloat16(f[2*q+1]);
                    hw[q] = packb2f(f[2*q], f[2*q+1]);
                    lw[q] = packb2f(f[2*q]   - __bfloat162float(h0),
                                    f[2*q+1] - __bfloat162float(h1));
                }
                uint32_t off = SWZ5((uint32_t)(klt * 512 + (kq * 32 + g * 8) * 2));
                *(uint4*)(smc + OFF_KH + off) = make_uint4(hw[0], hw[1], hw[2], hw[3]);
                *(uint4*)(smc + OFF_KL + off) = make_uint4(lw[0], lw[1], lw[2], lw[3]);
            }
        }
        __syncthreads();

        // ---- (b) Gram G = K K^T (bf16 split, 3 term) ----
        {
            float gacc[4] = {0.f, 0.f, 0.f, 0.f};
            const int mh = wid & 1, nq = wid >> 1;
            const uint32_t arow = (uint32_t)(16 * mh + (lid & 15)) * 512;
            const uint32_t asel = (uint32_t)((lid >> 4) << 4);
            const uint32_t brow = (uint32_t)(8 * nq + (lid & 7)) * 512;
            const uint32_t bsel = (uint32_t)(((lid >> 3) & 1) << 4);
            #pragma unroll
            for (int ks = 0; ks < 16; ++ks) {
                uint32_t ca = ks * 32;
                uint32_t agh[4], agl[4], gbh[2], gbl[2];
                ldsm_x4(agh, KH + SWZ5(arow + ca + asel));
                ldsm_x4(agl, KL + SWZ5(arow + ca + asel));
                ldsm_x2(gbh, KH + SWZ5(brow + ca + bsel));
                ldsm_x2(gbl, KL + SWZ5(brow + ca + bsel));
                mma_bf(gacc, agh, gbh[0], gbh[1]);
                mma_bf(gacc, agh, gbl[0], gbl[1]);
                mma_bf(gacc, agl, gbh[0], gbh[1]);
            }
            int t = 16 * mh + qm, s = 8 * nq + qn;
            sG[t*36 + s] = gacc[0]; sG[t*36 + s + 1] = gacc[1];
            sG[(t+8)*36 + s] = gacc[2]; sG[(t+8)*36 + s + 1] = gacc[3];
        }
        __syncthreads();

        // ---- (c1) per-t coefficients ----
        if (tid < 32) {
            float g = sG[tid*36 + tid];
            float s = 1.0f / (g + 1e-6f);
            sc[tid] = s;
            ct[tid] = s * spw[tid];
            wv[tid] = (tid < Cc) ? OMB * spw[Cc - 1 - tid] : 0.f;
        }
        __syncthreads();

        // ---- (c2) coupling coefs + (d) U = M K^T ----
        for (int p = tid; p < 1024; p += 256) {
            int t = p >> 5, s = p & 31;
            if (s < t) sA[p] = sG[t*36 + s] * sc[t] * OMB * spw[t - 1 - s];
        }
        {
            float uacc[4][4];
            #pragma unroll
            for (int f = 0; f < 4; ++f)
                #pragma unroll
                for (int q = 0; q < 4; ++q) uacc[f][q] = 0.f;
            const uint32_t mrow = (uint32_t)(16 * wid + (lid & 15)) * 512;
            const uint32_t asel = (uint32_t)((lid >> 4) << 4);
            const uint32_t brow0 = (uint32_t)(((lid >> 4) << 3) + (lid & 7)) * 512;
            const uint32_t brow1 = brow0 + 16 * 512;
            const uint32_t bsel = (uint32_t)(((lid >> 3) & 1) << 4);
            #pragma unroll
            for (int ks = 0; ks < 16; ++ks) {
                uint32_t ca = ks * 32;
                uint32_t amh[4], aml[4], b0h[4], b0l[4], b1h[4], b1l[4];
                ldsm_x4(amh, MH + SWZ5(mrow + ca + asel));
                ldsm_x4(aml, ML + SWZ5(mrow + ca + asel));
                ldsm_x4(b0h, KH + SWZ5(brow0 + ca + bsel));
                ldsm_x4(b0l, KL + SWZ5(brow0 + ca + bsel));
                ldsm_x4(b1h, KH + SWZ5(brow1 + ca + bsel));
                ldsm_x4(b1l, KL + SWZ5(brow1 + ca + bsel));
                #pragma unroll
                for (int f = 0; f < 4; ++f) {
                    const uint32_t* bh = (f < 2) ? b0h : b1h;
                    const uint32_t* bl = (f < 2) ? b0l : b1l;
                    int j = (f & 1) * 2;
                    mma_bf(uacc[f], amh, bh[j], bh[j+1]);
                    mma_bf(uacc[f], amh, bl[j], bl[j+1]);
                    mma_bf(uacc[f], aml, bh[j], bh[j+1]);
                }
            }
            // write raw U: sD[lt][i], warp rows i = 16*wid + qm(+8), lt = 8f + qn(+1)
            int i = 16 * wid + qm;
            #pragma unroll
            for (int f = 0; f < 4; ++f) {
                int lt = 8 * f + qn;
                sD[lt*128 + i]           = uacc[f][0];
                sD[(lt+1)*128 + i]       = uacc[f][1];
                sD[lt*128 + i + 8]       = uacc[f][2];
                sD[(lt+1)*128 + i + 8]   = uacc[f][3];
            }
        }
        __syncthreads();

        // ---- (e) triangular solve (threads 0..127, component i) ----
        if (tid < 128) {
            const int i = tid;
            float d[CH];
            const uint32_t coff = (uint32_t)((r0 + i) * 2);
            #pragma unroll
            for (int t = 0; t < CH; ++t) {
                uint32_t o = SWZ5((uint32_t)(t * 512) + coff);
                float rhs = bfu(*(const uint16_t*)(smc + OFF_KH + o))
                          + bfu(*(const uint16_t*)(smc + OFF_KL + o));
                d[t] = rhs - ct[t] * sD[t*128 + i];
            }
            #pragma unroll
            for (int s = 0; s < CH - 1; ++s)
                #pragma unroll
                for (int t = s + 1; t < CH; ++t)
                    d[t] -= sA[t*32 + s] * d[s];
            // weighted transpose store: dT[i][s] bf16 hi/lo, row stride 80B
            #pragma unroll
            for (int s = 0; s < CH; s += 2) {
                float w0 = d[s] * wv[s], w1 = d[s+1] * wv[s+1];
                __nv_bfloat16 h0 = __float2bfloat16(w0);
                __nv_bfloat16 h1 = __float2bfloat16(w1);
                *(uint32_t*)(smc + OFF_DTH + i*80 + s*2) = packb2f(w0, w1);
                *(uint32_t*)(smc + OFF_DTL + i*80 + s*2) =
                    packb2f(w0 - __bfloat162float(h0), w1 - __bfloat162float(h1));
            }
        }
        __syncthreads();

        // ---- (f) M update: acc = beta^Cc * acc + dT^T(weighted) @ K ----
        {
            float bc = spw[Cc];
            #pragma unroll
            for (int f = 0; f < 32; ++f)
                #pragma unroll
                for (int q = 0; q < 4; ++q) acc[f][q] *= bc;
            const uint32_t adbase = (uint32_t)(16 * wid + (lid & 15)) * 80
                                  + (uint32_t)((lid >> 4) << 4);
            const uint32_t tsel = (uint32_t)((lid >> 4) << 3) * 2;
            #pragma unroll
            for (int ks = 0; ks < 2; ++ks) {
                uint32_t adh[4], adl[4];
                ldsm_x4(adh, sb + OFF_DTH + adbase + ks * 32);
                ldsm_x4(adl, sb + OFF_DTL + adbase + ks * 32);
                uint32_t trow = (uint32_t)(ks * 16 + (lid & 15)) * 512;
                #pragma unroll
                for (int jg = 0; jg < 16; ++jg) {
                    uint32_t o = SWZ5(trow + jg * 32 + tsel);
                    uint32_t bth[4], btl[4];
                    ldsm_x4t(bth, KH + o);
                    ldsm_x4t(btl, KL + o);
                    mma_bf(acc[jg*2],   adh, bth[0], bth[1]);
                    mma_bf(acc[jg*2],   adh, btl[0], btl[1]);
                    mma_bf(acc[jg*2],   adl, bth[0], bth[1]);
                    mma_bf(acc[jg*2+1], adh, bth[2], bth[3]);
                    mma_bf(acc[jg*2+1], adh, btl[2], btl[3]);
                    mma_bf(acc[jg*2+1], adl, bth[2], bth[3]);
                }
            }
        }

        // ---- (g) publish M as bf16 hi/lo for next chunk's U ----
        if (t0 + CH < TT) {
            int r1 = 16 * wid + qm;
            #pragma unroll
            for (int f = 0; f < 32; ++f) {
                int c = f * 8 + qn;
                __nv_bfloat16 h0 = __float2bfloat16(acc[f][0]);
                __nv_bfloat16 h1 = __float2bfloat16(acc[f][1]);
                uint32_t o1 = SWZ5((uint32_t)(r1 * 512 + c * 2));
                *(uint32_t*)(smc + OFF_MH + o1) = packb2f(acc[f][0], acc[f][1]);
                *(uint32_t*)(smc + OFF_ML + o1) =
                    packb2f(acc[f][0] - __bfloat162float(h0),
                            acc[f][1] - __bfloat162float(h1));
                __nv_bfloat16 h2 = __float2bfloat16(acc[f][2]);
                __nv_bfloat16 h3 = __float2bfloat16(acc[f][3]);
                uint32_t o2 = SWZ5((uint32_t)((r1 + 8) * 512 + c * 2));
                *(uint32_t*)(smc + OFF_MH + o2) = packb2f(acc[f][2], acc[f][3]);
                *(uint32_t*)(smc + OFF_ML + o2) =
                    packb2f(acc[f][2] - __bfloat162float(h2),
                            acc[f][3] - __bfloat162float(h3));
            }
        }
    }

    // ---- final: stage fp32 M into smem (reuse sM region), write g_M ----
    __syncthreads();
    {
        float* SF = (float*)smc;   // [128][256] f32 = 131072 B
        int r1 = 16 * wid + qm;
        #pragma unroll
        for (int f = 0; f < 32; ++f) {
            int c = f * 8 + qn;
            SF[r1*256 + c]       = acc[f][0];
            SF[r1*256 + c + 1]   = acc[f][1];
            SF[(r1+8)*256 + c]   = acc[f][2];
            SF[(r1+8)*256 + c+1] = acc[f][3];
        }
        __syncthreads();
        const float4* sp = (const float4*)SF;
        for (int q = tid; q < 128 * 64; q += 256) {
            int i = q >> 6, j4 = q & 63;
            ((float4*)(g_M + ((size_t)b * HH + r0 + i) * HH))[j4] = sp[i*64 + j4];
        }
    }
}

// ---------------- 5-7. readout (unchanged) ----------------
__global__ void k_read1() {
    int b = blockIdx.x;
    int tid = threadIdx.x;
    __shared__ float hl[HH];
    hl[tid] = g_h[((size_t)b * LL + (LL - 1)) * HH + tid];
    __syncthreads();
    int w = tid >> 5, lane = tid & 31;
    for (int i = w; i < HH; i += 8) {
        const float* Mr = g_M + ((size_t)b * HH + i) * HH;
        float s = 0.f;
        #pragma unroll
        for (int j = lane; j < HH; j += 32) s += Mr[j] * hl[j];
        #pragma unroll
        for (int o = 16; o; o >>= 1) s += __shfl_xor_sync(0xffffffffu, s, o);
        if (lane == 0) g_y[b * HH + i] = s;
    }
}
__global__ void k_read2(const float* __restrict__ rp_W, const float* __restrict__ rp_b) {
    int b = blockIdx.x, n = threadIdx.x;
    __shared__ float ys[HH];
    ys[n] = g_y[b * HH + n];
    __syncthreads();
    float acc = rp_b[n];
    #pragma unroll 4
    for (int k = 0; k < HH; ++k) acc += ys[k] * rp_W[k * HH + n];
    g_y2[b * HH + n] = acc;
}

static constexpr int OUT_SMEM_BYTES = (HH * 128 + BB * 257) * 4;

__global__ __launch_bounds__(256) void k_out(
    const float* __restrict__ out_W, const float* __restrict__ out_b,
    float* __restrict__ out)
{
    extern __shared__ float smf[];
    float* sW  = smf;
    float* sy2 = smf + HH * 128;
    int tid = threadIdx.x;
    int n_base = blockIdx.x * 128;

    for (int idx = tid; idx < HH * 32; idx += 256) {
        int k = idx >> 5, q = idx & 31;
        *(float4*)(sW + k*128 + q*4) = *(const float4*)(out_W + (size_t)k * VV + n_base + q*4);
    }
    for (int idx = tid; idx < BB * 64; idx += 256) {
        int bb = idx >> 6, q = idx & 63;
        float4 v = *(const float4*)(g_y2 + bb * HH + q*4);
        float* d = sy2 + bb*257 + q*4;
        d[0] = v.x; d[1] = v.y; d[2] = v.z; d[3] = v.w;
    }
    __syncthreads();

    int bg = tid >> 4, ng = tid & 15;
    int b0 = bg * 4, n0 = ng * 8;
    float acc[4][8];
    #pragma unroll
    for (int r = 0; r < 4; ++r)
        #pragma unroll
        for (int c = 0; c < 8; ++c) acc[r][c] = 0.f;
    for (int k = 0; k < HH; ++k) {
        float4 w0 = *(const float4*)(sW + k*128 + n0);
        float4 w1 = *(const float4*)(sW + k*128 + n0 + 4);
        float wv[8] = {w0.x, w0.y, w0.z, w0.w, w1.x, w1.y, w1.z, w1.w};
        #pragma unroll
        for (int r = 0; r < 4; ++r) {
            float yv = sy2[(b0+r)*257 + k];
            #pragma unroll
            for (int c = 0; c < 8; ++c) acc[r][c] += yv * wv[c];
        }
    }
    #pragma unroll
    for (int r = 0; r < 4; ++r)
        #pragma unroll
        for (int c = 0; c < 8; ++c)
            out[(size_t)(b0+r) * VV + n_base + n0 + c] = acc[r][c] + out_b[n_base + n0 + c];
}

// ---------------- launch ----------------
extern "C" void kernel_launch(void* const* d_in, const int* in_sizes, int n_in,
                              void* d_out, int out_size) {
    (void)in_sizes; (void)n_in; (void)out_size;
    const int*   seq     = (const int*)  d_in[0];
    const float* embed   = (const float*)d_in[1];
    const float* W1      = (const float*)d_in[2];
    const float* b1      = (const float*)d_in[3];
    const float* W2      = (const float*)d_in[4];
    const float* b2      = (const float*)d_in[5];
    const float* gamma   = (const float*)d_in[6];
    const float* beta_ln = (const float*)d_in[7];
    const float* rp_W    = (const float*)d_in[8];
    const float* rp_b    = (const float*)d_in[9];
    const float* out_W   = (const float*)d_in[10];
    const float* out_b   = (const float*)d_in[11];
    float* out = (float*)d_out;

    cudaFuncSetAttribute(k_ffn<1>, cudaFuncAttributeMaxDynamicSharedMemorySize, FFN_SMEM);
    cudaFuncSetAttribute(k_ffn<2>, cudaFuncAttributeMaxDynamicSharedMemorySize, FFN_SMEM);
    cudaFuncSetAttribute(k_scan,   cudaFuncAttributeMaxDynamicSharedMemorySize, SCAN_SMEM_BYTES);
    cudaFuncSetAttribute(k_out,    cudaFuncAttributeMaxDynamicSharedMemorySize, OUT_SMEM_BYTES);

    k_prep<<<512, 256>>>(W1, W2);
    k_split<<<BB * LL * 64 / 256, 256>>>(seq, embed);
    k_ffn<1><<<dim3(4, BB*LL/128), 256, FFN_SMEM>>>(seq, embed, b1);
    k_ffn<2><<<dim3(2, BB*LL/128), 256, FFN_SMEM>>>(seq, embed, b2);
    k_ln<<<BB * LL / 8, 256>>>(gamma, beta_ln);
    k_scan<<<BB * 2, 256, SCAN_SMEM_BYTES>>>();
    k_read1<<<BB, 256>>>();
    k_read2<<<BB, HH>>>(rp_W, rp_b);
    k_out<<<VV / 128, 256, OUT_SMEM_BYTES>>>(out_W, out_b, out);
}

// round 9
// speedup vs baseline: 2.7684x; 1.1034x over previous
#include <cuda_runtime.h>
#include <cuda_fp16.h>
#include <cuda_bf16.h>
#include <math.h>
#include <stdint.h>

static constexpr int BB = 64;
static constexpr int LL = 2048;
static constexpr int HH = 256;
static constexpr int VV = 32000;
static constexpr int TT = LL - 1;
static constexpr float BETA = 0.9f;
static constexpr float OMB  = 0.1f;
static constexpr int CH = 32;

// ---------------- scratch ----------------
__device__ float  g_h [(size_t)BB*LL*HH];
__device__ __half g_af[(size_t)BB*LL*HH];       // tiled-swizzled fp16 A for ffn1
__device__ __half g_ff[(size_t)BB*LL*2*HH];     // tiled-swizzled fp16 A for ffn2
__device__ __half g_w1t[512*256];               // tiled-swizzled W1^T
__device__ __half g_w2t[256*512];               // tiled-swizzled W2^T
__device__ float  g_M [(size_t)BB*HH*HH];
__device__ float  g_y [BB*HH];
__device__ float  g_y2[BB*HH];

#define SWZ(o)  ((o) ^ (((o) >> 3) & 0x70))   // 128B rows
#define SWZ5(o) ((o) ^ (((o) >> 5) & 0x70))   // 512B rows

__device__ __forceinline__ uint32_t smem_u32(const void* p) {
    uint32_t a;
    asm("{ .reg .u64 t; cvta.to.shared.u64 t, %1; cvt.u32.u64 %0, t; }" : "=r"(a) : "l"(p));
    return a;
}
__device__ __forceinline__ uint32_t packh2(float a, float b) {
    __half2 t = __floats2half2_rn(a, b);
    return *reinterpret_cast<uint32_t*>(&t);
}
__device__ __forceinline__ uint32_t packb2f(float a, float b) {
    __nv_bfloat162 t = __floats2bfloat162_rn(a, b);
    return *reinterpret_cast<uint32_t*>(&t);
}
__device__ __forceinline__ float bfu(uint16_t h) {
    return __uint_as_float(((uint32_t)h) << 16);
}
__device__ __forceinline__ void ldsm_x4(uint32_t* r, uint32_t addr) {
    asm volatile("ldmatrix.sync.aligned.m8n8.x4.shared.b16 {%0,%1,%2,%3}, [%4];"
        : "=r"(r[0]), "=r"(r[1]), "=r"(r[2]), "=r"(r[3]) : "r"(addr));
}
__device__ __forceinline__ void ldsm_x4t(uint32_t* r, uint32_t addr) {
    asm volatile("ldmatrix.sync.aligned.m8n8.x4.trans.shared.b16 {%0,%1,%2,%3}, [%4];"
        : "=r"(r[0]), "=r"(r[1]), "=r"(r[2]), "=r"(r[3]) : "r"(addr));
}
__device__ __forceinline__ void ldsm_x2(uint32_t* r, uint32_t addr) {
    asm volatile("ldmatrix.sync.aligned.m8n8.x2.shared.b16 {%0,%1}, [%2];"
        : "=r"(r[0]), "=r"(r[1]) : "r"(addr));
}
__device__ __forceinline__ void mma_f16(float* d, const uint32_t* a, uint32_t b0, uint32_t b1) {
    asm volatile("mma.sync.aligned.m16n8k16.row.col.f32.f16.f16.f32 "
        "{%0,%1,%2,%3}, {%4,%5,%6,%7}, {%8,%9}, {%0,%1,%2,%3};"
        : "+f"(d[0]), "+f"(d[1]), "+f"(d[2]), "+f"(d[3])
        : "r"(a[0]), "r"(a[1]), "r"(a[2]), "r"(a[3]), "r"(b0), "r"(b1));
}
__device__ __forceinline__ void mma_bf(float* d, const uint32_t* a, uint32_t b0, uint32_t b1) {
    asm volatile("mma.sync.aligned.m16n8k16.row.col.f32.bf16.bf16.f32 "
        "{%0,%1,%2,%3}, {%4,%5,%6,%7}, {%8,%9}, {%0,%1,%2,%3};"
        : "+f"(d[0]), "+f"(d[1]), "+f"(d[2]), "+f"(d[3])
        : "r"(a[0]), "r"(a[1]), "r"(a[2]), "r"(a[3]), "r"(b0), "r"(b1));
}

#define MBAR_INIT(a, cnt) \
    asm volatile("mbarrier.init.shared.b64 [%0], %1;" :: "r"((uint32_t)(a)), "r"((uint32_t)(cnt)) : "memory")
#define MBAR_TX(a, bytes) \
    asm volatile("mbarrier.arrive.expect_tx.shared.b64 _, [%0], %1;" :: "r"((uint32_t)(a)), "r"((uint32_t)(bytes)) : "memory")
#define BULK(dst, src, bytes, mbar) \
    asm volatile("cp.async.bulk.shared::cta.global.mbarrier::complete_tx::bytes [%0], [%1], %2, [%3];" \
        :: "r"((uint32_t)(dst)), "l"(src), "r"((uint32_t)(bytes)), "r"((uint32_t)(mbar)) : "memory")
#define MBAR_WAIT(a, par) do {                                                    \
    uint32_t _m = (uint32_t)(a); uint32_t _p = (uint32_t)(par); uint32_t _d;      \
    asm volatile("{\n\t.reg .pred p;\n\t"                                         \
        "mbarrier.try_wait.parity.acquire.cta.shared::cta.b64 p, [%1], %2;\n\t"   \
        "selp.b32 %0, 1, 0, p;\n\t}"                                              \
        : "=r"(_d) : "r"(_m), "r"(_p) : "memory");                                \
    if (!_d) {                                                                    \
        asm volatile("{\n\t.reg .pred P1;\n\t"                                    \
            "WL_%=:\n\t"                                                          \
            "mbarrier.try_wait.parity.acquire.cta.shared::cta.b64 P1, [%0], %1, 0x989680;\n\t" \
            "@P1 bra.uni WD_%=;\n\t"                                              \
            "bra.uni WL_%=;\n\t"                                                  \
            "WD_%=:\n\t}"                                                         \
            :: "r"(_m), "r"(_p) : "memory");                                      \
    }                                                                             \
} while (0)

// ---------------- 0a. weights -> fp16, tiled-swizzled 16KB tiles ----------------
__global__ void k_prep(const float* __restrict__ W1, const float* __restrict__ W2) {
    int idx = blockIdx.x * blockDim.x + threadIdx.x;   // 0..131071
    {   // W1t: tile (nb= n>>7, c= k>>6), within SWZ((n&127)*128 + (k&63)*2)
        int n = idx >> 8, k = idx & 255;
        __half v = __float2half_rn(W1[k * 512 + n]);
        size_t off = (((size_t)(n >> 7) * 4 + (k >> 6)) << 14)
                   + SWZ((uint32_t)((n & 127) * 128 + (k & 63) * 2));
        *(__half*)((char*)g_w1t + off) = v;
    }
    {   // W2t: tiles (nb= n>>7 in [0,2), c= k>>6 in [0,8))
        int n = idx >> 9, k = idx & 511;
        __half v = __float2half_rn(W2[k * 256 + n]);
        size_t off = (((size_t)(n >> 7) * 8 + (k >> 6)) << 14)
                   + SWZ((uint32_t)((n & 127) * 128 + (k & 63) * 2));
        *(__half*)((char*)g_w2t + off) = v;
    }
}

// ---------------- 0b. gather -> fp16 tiled-swizzled ----------------
__global__ void k_split(const int* __restrict__ seq, const float* __restrict__ embed) {
    size_t idx = (size_t)blockIdx.x * blockDim.x + threadIdx.x;   // B*L*32
    int row = (int)(idx >> 5), g = (int)(idx & 31);
    int tok = seq[row];
    const float4* src = (const float4*)(embed + (size_t)tok * HH + g * 8);
    float4 v0 = src[0], v1 = src[1];
    uint4 o = make_uint4(packh2(v0.x, v0.y), packh2(v0.z, v0.w),
                         packh2(v1.x, v1.y), packh2(v1.z, v1.w));
    int mt = row >> 7, c = g >> 3;
    size_t off = (((size_t)mt * 4 + c) << 14)
               + SWZ((uint32_t)((row & 127) * 128 + (g & 7) * 16));
    *(uint4*)((char*)g_af + off) = o;
}

// ---------------- 1+2. FFN: fp16 HMMA + cp.async.bulk double-buffer ----------------
static constexpr int FFN_SMEM = 1024 + 65536 + 64;

__device__ __forceinline__ void ffn_compute(uint32_t aB, uint32_t bB,
                                            int wm, int wn, int lid, float (&acc)[4][4][4])
{
    #pragma unroll
    for (int ks = 0; ks < 4; ++ks) {
        uint32_t colA = ks * 32 + ((lid >> 4) << 4);
        uint32_t ah[4][4];
        #pragma unroll
        for (int mf = 0; mf < 4; ++mf) {
            uint32_t row = wm * 64 + mf * 16 + (lid & 15);
            ldsm_x4(ah[mf], aB + SWZ(row * 128 + colA));
        }
        uint32_t bh[2][4];
        #pragma unroll
        for (int nf = 0; nf < 2; ++nf) {
            uint32_t row = wn * 32 + nf * 16 + ((lid >> 4) << 3) + (lid & 7);
            uint32_t colB = ks * 32 + (((lid >> 3) & 1) << 4);
            ldsm_x4(bh[nf], bB + SWZ(row * 128 + colB));
        }
        #pragma unroll
        for (int mf = 0; mf < 4; ++mf)
            #pragma unroll
            for (int nf = 0; nf < 2; ++nf)
                #pragma unroll
                for (int j = 0; j < 2; ++j)
                    mma_f16(acc[mf][nf*2+j], ah[mf], bh[nf][j*2], bh[nf][j*2+1]);
    }
}

template<int PHASE>
__global__ __launch_bounds__(256, 2) void k_ffn(
    const int* __restrict__ seq, const float* __restrict__ embed,
    const float* __restrict__ bias)
{
    constexpr int NC = (PHASE == 1) ? 4 : 8;

    extern __shared__ char sm[];
    int*   sseq  = (int*)sm;
    float* sbias = (float*)(sm + 512);
    const uint32_t sb = smem_u32(sm);
    const uint32_t st0 = sb + 1024, st1 = sb + 1024 + 32768;
    const uint32_t mb  = sb + 1024 + 65536;   // two mbarriers

    const int tid = threadIdx.x, wid = tid >> 5, lid = tid & 31;
    const int wm = wid & 1, wn = wid >> 1;
    const int mt = blockIdx.y, nb0 = blockIdx.x * 128;

    const char* Atl = (const char*)((PHASE == 1) ? (const void*)g_af : (const void*)g_ff)
                    + (((size_t)mt * NC) << 14);
    const char* Btl = (const char*)((PHASE == 1) ? (const void*)g_w1t : (const void*)g_w2t)
                    + (((size_t)blockIdx.x * NC) << 14);

    if (tid < 128) {
        sbias[tid] = bias[nb0 + tid];
        if (PHASE == 2) sseq[tid] = seq[mt * 128 + tid];
    }
    if (tid == 0) { MBAR_INIT(mb, 1); MBAR_INIT(mb + 8, 1); }
    __syncthreads();

    if (tid == 0) {
        MBAR_TX(mb, 32768);
        BULK(st0, Atl, 16384, mb);
        BULK(st0 + 16384, Btl, 16384, mb);
        MBAR_TX(mb + 8, 32768);
        BULK(st1, Atl + 16384, 16384, mb + 8);
        BULK(st1 + 16384, Btl + 16384, 16384, mb + 8);
    }

    float acc[4][4][4];
    #pragma unroll
    for (int a = 0; a < 4; ++a)
        #pragma unroll
        for (int b = 0; b < 4; ++b)
            #pragma unroll
            for (int c = 0; c < 4; ++c) acc[a][b][c] = 0.f;

    for (int c = 0; c < NC; ++c) {
        int s = c & 1;
        uint32_t stg = s ? st1 : st0;
        MBAR_WAIT(mb + s * 8, (c >> 1) & 1);
        ffn_compute(stg, stg + 16384, wm, wn, lid, acc);
        __syncthreads();
        if (tid == 0 && c + 2 < NC) {
            MBAR_TX(mb + s * 8, 32768);
            BULK(stg, Atl + ((size_t)(c + 2) << 14), 16384, mb + s * 8);
            BULK(stg + 16384, Btl + ((size_t)(c + 2) << 14), 16384, mb + s * 8);
        }
    }

    const int qm = lid >> 2, qn = (lid & 3) * 2;
    if (PHASE == 1) {
        // stage relu(acc+bias) as half2 in [128][64] uints, then write 2 swizzled 16KB tiles
        uint32_t* SH = (uint32_t*)(sm + 1024);
        #pragma unroll
        for (int mf = 0; mf < 4; ++mf)
            #pragma unroll
            for (int nf = 0; nf < 2; ++nf)
                #pragma unroll
                for (int j = 0; j < 2; ++j) {
                    const float* d = acc[mf][nf*2+j];
                    int nl = wn * 32 + nf * 16 + j * 8 + qn;
                    #pragma unroll
                    for (int hh = 0; hh < 2; ++hh) {
                        int ml = wm * 64 + mf * 16 + qm + hh * 8;
                        float v0 = fmaxf(d[hh*2+0] + sbias[nl],   0.f);
                        float v1 = fmaxf(d[hh*2+1] + sbias[nl+1], 0.f);
                        SH[ml * 64 + (nl >> 1)] = packh2(v0, v1);
                    }
                }
        __syncthreads();
        char* gff = (char*)g_ff;
        #pragma unroll
        for (int t = 0; t < 8; ++t) {
            int idx = t * 256 + tid;            // 0..2047
            int tile = idx >> 10, rem = idx & 1023;
            int r = rem >> 3, j = rem & 7;
            uint4 v = ((const uint4*)SH)[r * 16 + tile * 8 + j];
            size_t off = (((size_t)mt * 8 + blockIdx.x * 2 + tile) << 14)
                       + SWZ((uint32_t)(r * 128 + j * 16));
            *(uint4*)(gff + off) = v;
        }
    } else {
        float* SF = (float*)(sm + 1024);        // [128][128] f32
        #pragma unroll
        for (int mf = 0; mf < 4; ++mf)
            #pragma unroll
            for (int nf = 0; nf < 2; ++nf)
                #pragma unroll
                for (int j = 0; j < 2; ++j) {
                    const float* d = acc[mf][nf*2+j];
                    int nl = wn * 32 + nf * 16 + j * 8 + qn;
                    #pragma unroll
                    for (int hh = 0; hh < 2; ++hh) {
                        int ml = wm * 64 + mf * 16 + qm + hh * 8;
                        SF[ml * 128 + nl]     = d[hh*2+0] + sbias[nl];
                        SF[ml * 128 + nl + 1] = d[hh*2+1] + sbias[nl+1];
                    }
                }
        __syncthreads();
        int row = tid >> 1, part = tid & 1;
        int tok = sseq[row];
        const float4* ep = (const float4*)(embed + (size_t)tok * HH + nb0);
        const float4* sfp = (const float4*)(SF + row * 128);
        float4* gp = (float4*)(g_h + ((size_t)mt * 128 + row) * HH + nb0);
        #pragma unroll
        for (int j = 0; j < 16; ++j) {
            int c4 = part * 16 + j;
            float4 f = sfp[c4];
            float4 e = ep[c4];
            f.x += e.x; f.y += e.y; f.z += e.z; f.w += e.w;
            gp[c4] = f;
        }
    }
}

// ---------------- 3. LayerNorm (unchanged) ----------------
__global__ void k_ln(const float* __restrict__ gamma, const float* __restrict__ beta_ln) {
    int warp = threadIdx.x >> 5, lane = threadIdx.x & 31;
    size_t row = (size_t)blockIdx.x * 8 + warp;
    float4* xp = (float4*)(g_h + row * HH);
    float4 a = xp[lane * 2];
    float4 b = xp[lane * 2 + 1];
    float s = a.x + a.y + a.z + a.w + b.x + b.y + b.z + b.w;
    #pragma unroll
    for (int o = 16; o; o >>= 1) s += __shfl_xor_sync(0xffffffffu, s, o);
    float mu = s * (1.0f / HH);
    float dx[8] = {a.x-mu, a.y-mu, a.z-mu, a.w-mu, b.x-mu, b.y-mu, b.z-mu, b.w-mu};
    float v = 0.f;
    #pragma unroll
    for (int q = 0; q < 8; ++q) v += dx[q] * dx[q];
    #pragma unroll
    for (int o = 16; o; o >>= 1) v += __shfl_xor_sync(0xffffffffu, v, o);
    float inv = rsqrtf(v * (1.0f / HH) + 1e-5f);
    float4 g0 = ((const float4*)gamma)[lane * 2];
    float4 g1 = ((const float4*)gamma)[lane * 2 + 1];
    float4 t0 = ((const float4*)beta_ln)[lane * 2];
    float4 t1 = ((const float4*)beta_ln)[lane * 2 + 1];
    float4 o0, o1;
    o0.x = dx[0]*inv*g0.x + t0.x; o0.y = dx[1]*inv*g0.y + t0.y;
    o0.z = dx[2]*inv*g0.z + t0.z; o0.w = dx[3]*inv*g0.w + t0.w;
    o1.x = dx[4]*inv*g1.x + t1.x; o1.y = dx[5]*inv*g1.y + t1.y;
    o1.z = dx[6]*inv*g1.z + t1.z; o1.w = dx[7]*inv*g1.w + t1.w;
    xp[lane * 2]     = o0;
    xp[lane * 2 + 1] = o1;
}

// ---------------- 4. scan: HMMA chunked delta rule (unchanged from round 8) ----------------
static constexpr uint32_t OFF_MH  = 0;
static constexpr uint32_t OFF_ML  = 65536;
static constexpr uint32_t OFF_KH  = 131072;
static constexpr uint32_t OFF_KL  = 147456;
static constexpr uint32_t OFF_SD  = 163840;
static constexpr uint32_t OFF_DTH = 180224;
static constexpr uint32_t OFF_DTL = 190464;
static constexpr uint32_t OFF_G   = 200704;
static constexpr uint32_t OFF_A   = 205312;
static constexpr uint32_t OFF_SC  = 209408;
static constexpr int SCAN_SMEM_BYTES = 210048;

__global__ __launch_bounds__(256, 1) void k_scan() {
    extern __shared__ char smc[];
    const uint32_t sb = smem_u32(smc);
    const uint32_t MH = sb + OFF_MH, ML = sb + OFF_ML;
    const uint32_t KH = sb + OFF_KH, KL = sb + OFF_KL;
    float* sD  = (float*)(smc + OFF_SD);
    float* sG  = (float*)(smc + OFF_G);
    float* sA  = (float*)(smc + OFF_A);
    float* sc  = (float*)(smc + OFF_SC);
    float* ct  = sc + 32;
    float* wv  = ct + 32;
    float* spw = wv + 32;

    const int tid = threadIdx.x, wid = tid >> 5, lid = tid & 31;
    const int qm = lid >> 2, qn = (lid & 3) * 2;
    const int b  = blockIdx.x >> 1;
    const int r0 = (blockIdx.x & 1) * 128;
    const float* hb = g_h + (size_t)b * LL * HH;

    for (int i = tid; i < 131072 / 16; i += 256)
        ((uint4*)(smc + OFF_MH))[i] = make_uint4(0, 0, 0, 0);
    if (tid == 0) {
        spw[0] = 1.f;
        for (int i = 1; i <= CH; ++i) spw[i] = spw[i-1] * BETA;
    }
    __syncthreads();

    float acc[32][4];
    #pragma unroll
    for (int f = 0; f < 32; ++f)
        #pragma unroll
        for (int q = 0; q < 4; ++q) acc[f][q] = 0.f;

    const int klt = tid >> 3, kq = tid & 7;

    for (int t0 = 0; t0 < TT; t0 += CH) {
        const int Cc = min(CH, TT - t0);
        __syncthreads();

        {
            const float* src = hb + (size_t)(t0 + klt) * HH + kq * 32;
            bool pad = (klt >= Cc);
            #pragma unroll
            for (int g = 0; g < 4; ++g) {
                float f[8];
                if (pad) {
                    #pragma unroll
                    for (int q = 0; q < 8; ++q) f[q] = 0.f;
                } else {
                    float4 v0 = *(const float4*)(src + g*8);
                    float4 v1 = *(const float4*)(src + g*8 + 4);
                    f[0]=v0.x; f[1]=v0.y; f[2]=v0.z; f[3]=v0.w;
                    f[4]=v1.x; f[5]=v1.y; f[6]=v1.z; f[7]=v1.w;
                }
                uint32_t hw[4], lw[4];
                #pragma unroll
                for (int q = 0; q < 4; ++q) {
                    __nv_bfloat16 h0 = __float2bfloat16(f[2*q]);
                    __nv_bfloat16 h1 = __float2bfloat16(f[2*q+1]);
                    hw[q] = packb2f(f[2*q], f[2*q+1]);
                    lw[q] = packb2f(f[2*q]   - __bfloat162float(h0),
                                    f[2*q+1] - __bfloat162float(h1));
                }
                uint32_t off = SWZ5((uint32_t)(klt * 512 + (kq * 32 + g * 8) * 2));
                *(uint4*)(smc + OFF_KH + off) = make_uint4(hw[0], hw[1], hw[2], hw[3]);
                *(uint4*)(smc + OFF_KL + off) = make_uint4(lw[0], lw[1], lw[2], lw[3]);
            }
        }
        __syncthreads();

        {
            float gacc[4] = {0.f, 0.f, 0.f, 0.f};
            const int mh = wid & 1, nq = wid >> 1;
            const uint32_t arow = (uint32_t)(16 * mh + (lid & 15)) * 512;
            const uint32_t asel = (uint32_t)((lid >> 4) << 4);
            const uint32_t brow = (uint32_t)(8 * nq + (lid & 7)) * 512;
            const uint32_t bsel = (uint32_t)(((lid >> 3) & 1) << 4);
            #pragma unroll
            for (int ks = 0; ks < 16; ++ks) {
                uint32_t ca = ks * 32;
                uint32_t agh[4], agl[4], gbh[2], gbl[2];
                ldsm_x4(agh, KH + SWZ5(arow + ca + asel));
                ldsm_x4(agl, KL + SWZ5(arow + ca + asel));
                ldsm_x2(gbh, KH + SWZ5(brow + ca + bsel));
                ldsm_x2(gbl, KL + SWZ5(brow + ca + bsel));
                mma_bf(gacc, agh, gbh[0], gbh[1]);
                mma_bf(gacc, agh, gbl[0], gbl[1]);
                mma_bf(gacc, agl, gbh[0], gbh[1]);
            }
            int t = 16 * mh + qm, s = 8 * nq + qn;
            sG[t*36 + s] = gacc[0]; sG[t*36 + s + 1] = gacc[1];
            sG[(t+8)*36 + s] = gacc[2]; sG[(t+8)*36 + s + 1] = gacc[3];
        }
        __syncthreads();

        if (tid < 32) {
            float g = sG[tid*36 + tid];
            float s = 1.0f / (g + 1e-6f);
            sc[tid] = s;
            ct[tid] = s * spw[tid];
            wv[tid] = (tid < Cc) ? OMB * spw[Cc - 1 - tid] : 0.f;
        }
        __syncthreads();

        for (int p = tid; p < 1024; p += 256) {
            int t = p >> 5, s = p & 31;
            if (s < t) sA[p] = sG[t*36 + s] * sc[t] * OMB * spw[t - 1 - s];
        }
        {
            float uacc[4][4];
            #pragma unroll
            for (int f = 0; f < 4; ++f)
                #pragma unroll
                for (int q = 0; q < 4; ++q) uacc[f][q] = 0.f;
            const uint32_t mrow = (uint32_t)(16 * wid + (lid & 15)) * 512;
            const uint32_t asel = (uint32_t)((lid >> 4) << 4);
            const uint32_t brow0 = (uint32_t)(((lid >> 4) << 3) + (lid & 7)) * 512;
            const uint32_t brow1 = brow0 + 16 * 512;
            const uint32_t bsel = (uint32_t)(((lid >> 3) & 1) << 4);
            #pragma unroll
            for (int ks = 0; ks < 16; ++ks) {
                uint32_t ca = ks * 32;
                uint32_t amh[4], aml[4], b0h[4], b0l[4], b1h[4], b1l[4];
                ldsm_x4(amh, MH + SWZ5(mrow + ca + asel));
                ldsm_x4(aml, ML + SWZ5(mrow + ca + asel));
                ldsm_x4(b0h, KH + SWZ5(brow0 + ca + bsel));
                ldsm_x4(b0l, KL + SWZ5(brow0 + ca + bsel));
                ldsm_x4(b1h, KH + SWZ5(brow1 + ca + bsel));
                ldsm_x4(b1l, KL + SWZ5(brow1 + ca + bsel));
                #pragma unroll
                for (int f = 0; f < 4; ++f) {
                    const uint32_t* bh = (f < 2) ? b0h : b1h;
                    const uint32_t* bl = (f < 2) ? b0l : b1l;
                    int j = (f & 1) * 2;
                    mma_bf(uacc[f], amh, bh[j], bh[j+1]);
                    mma_bf(uacc[f], amh, bl[j], bl[j+1]);
                    mma_bf(uacc[f], aml, bh[j], bh[j+1]);
                }
            }
            int i = 16 * wid + qm;
            #pragma unroll
            for (int f = 0; f < 4; ++f) {
                int lt = 8 * f + qn;
                sD[lt*128 + i]           = uacc[f][0];
                sD[(lt+1)*128 + i]       = uacc[f][1];
                sD[lt*128 + i + 8]       = uacc[f][2];
                sD[(lt+1)*128 + i + 8]   = uacc[f][3];
            }
        }
        __syncthreads();

        if (tid < 128) {
            const int i = tid;
            float d[CH];
            const uint32_t coff = (uint32_t)((r0 + i) * 2);
            #pragma unroll
            for (int t = 0; t < CH; ++t) {
                uint32_t o = SWZ5((uint32_t)(t * 512) + coff);
                float rhs = bfu(*(const uint16_t*)(smc + OFF_KH + o))
                          + bfu(*(const uint16_t*)(smc + OFF_KL + o));
                d[t] = rhs - ct[t] * sD[t*128 + i];
            }
            #pragma unroll
            for (int s = 0; s < CH - 1; ++s)
                #pragma unroll
                for (int t = s + 1; t < CH; ++t)
                    d[t] -= sA[t*32 + s] * d[s];
            #pragma unroll
            for (int s = 0; s < CH; s += 2) {
                float w0 = d[s] * wv[s], w1 = d[s+1] * wv[s+1];
                __nv_bfloat16 h0 = __float2bfloat16(w0);
                __nv_bfloat16 h1 = __float2bfloat16(w1);
                *(uint32_t*)(smc + OFF_DTH + i*80 + s*2) = packb2f(w0, w1);
                *(uint32_t*)(smc + OFF_DTL + i*80 + s*2) =
                    packb2f(w0 - __bfloat162float(h0), w1 - __bfloat162float(h1));
            }
        }
        __syncthreads();

        {
            float bc = spw[Cc];
            #pragma unroll
            for (int f = 0; f < 32; ++f)
                #pragma unroll
                for (int q = 0; q < 4; ++q) acc[f][q] *= bc;
            const uint32_t adbase = (uint32_t)(16 * wid + (lid & 15)) * 80
                                  + (uint32_t)((lid >> 4) << 4);
            const uint32_t tsel = (uint32_t)((lid >> 4) << 3) * 2;
            #pragma unroll
            for (int ks = 0; ks < 2; ++ks) {
                uint32_t adh[4], adl[4];
                ldsm_x4(adh, sb + OFF_DTH + adbase + ks * 32);
                ldsm_x4(adl, sb + OFF_DTL + adbase + ks * 32);
                uint32_t trow = (uint32_t)(ks * 16 + (lid & 15)) * 512;
                #pragma unroll
                for (int jg = 0; jg < 16; ++jg) {
                    uint32_t o = SWZ5(trow + jg * 32 + tsel);
                    uint32_t bth[4], btl[4];
                    ldsm_x4t(bth, KH + o);
                    ldsm_x4t(btl, KL + o);
                    mma_bf(acc[jg*2],   adh, bth[0], bth[1]);
                    mma_bf(acc[jg*2],   adh, btl[0], btl[1]);
                    mma_bf(acc[jg*2],   adl, bth[0], bth[1]);
                    mma_bf(acc[jg*2+1], adh, bth[2], bth[3]);
                    mma_bf(acc[jg*2+1], adh, btl[2], btl[3]);
                    mma_bf(acc[jg*2+1], adl, bth[2], bth[3]);
                }
            }
        }

        if (t0 + CH < TT) {
            int r1 = 16 * wid + qm;
            #pragma unroll
            for (int f = 0; f < 32; ++f) {
                int c = f * 8 + qn;
                __nv_bfloat16 h0 = __float2bfloat16(acc[f][0]);
                __nv_bfloat16 h1 = __float2bfloat16(acc[f][1]);
                uint32_t o1 = SWZ5((uint32_t)(r1 * 512 + c * 2));
                *(uint32_t*)(smc + OFF_MH + o1) = packb2f(acc[f][0], acc[f][1]);
                *(uint32_t*)(smc + OFF_ML + o1) =
                    packb2f(acc[f][0] - __bfloat162float(h0),
                            acc[f][1] - __bfloat162float(h1));
                __nv_bfloat16 h2 = __float2bfloat16(acc[f][2]);
                __nv_bfloat16 h3 = __float2bfloat16(acc[f][3]);
                uint32_t o2 = SWZ5((uint32_t)((r1 + 8) * 512 + c * 2));
                *(uint32_t*)(smc + OFF_MH + o2) = packb2f(acc[f][2], acc[f][3]);
                *(uint32_t*)(smc + OFF_ML + o2) =
                    packb2f(acc[f][2] - __bfloat162float(h2),
                            acc[f][3] - __bfloat162float(h3));
            }
        }
    }

    __syncthreads();
    {
        float* SF = (float*)smc;
        int r1 = 16 * wid + qm;
        #pragma unroll
        for (int f = 0; f < 32; ++f) {
            int c = f * 8 + qn;
            SF[r1*256 + c]       = acc[f][0];
            SF[r1*256 + c + 1]   = acc[f][1];
            SF[(r1+8)*256 + c]   = acc[f][2];
            SF[(r1+8)*256 + c+1] = acc[f][3];
        }
        __syncthreads();
        const float4* sp = (const float4*)SF;
        for (int q = tid; q < 128 * 64; q += 256) {
            int i = q >> 6, j4 = q & 63;
            ((float4*)(g_M + ((size_t)b * HH + r0 + i) * HH))[j4] = sp[i*64 + j4];
        }
    }
}

// ---------------- 5-7. readout (unchanged) ----------------
__global__ void k_read1() {
    int b = blockIdx.x;
    int tid = threadIdx.x;
    __shared__ float hl[HH];
    hl[tid] = g_h[((size_t)b * LL + (LL - 1)) * HH + tid];
    __syncthreads();
    int w = tid >> 5, lane = tid & 31;
    for (int i = w; i < HH; i += 8) {
        const float* Mr = g_M + ((size_t)b * HH + i) * HH;
        float s = 0.f;
        #pragma unroll
        for (int j = lane; j < HH; j += 32) s += Mr[j] * hl[j];
        #pragma unroll
        for (int o = 16; o; o >>= 1) s += __shfl_xor_sync(0xffffffffu, s, o);
        if (lane == 0) g_y[b * HH + i] = s;
    }
}
__global__ void k_read2(const float* __restrict__ rp_W, const float* __restrict__ rp_b) {
    int b = blockIdx.x, n = threadIdx.x;
    __shared__ float ys[HH];
    ys[n] = g_y[b * HH + n];
    __syncthreads();
    float acc = rp_b[n];
    #pragma unroll 4
    for (int k = 0; k < HH; ++k) acc += ys[k] * rp_W[k * HH + n];
    g_y2[b * HH + n] = acc;
}

static constexpr int OUT_SMEM_BYTES = (HH * 128 + BB * 257) * 4;

__global__ __launch_bounds__(256) void k_out(
    const float* __restrict__ out_W, const float* __restrict__ out_b,
    float* __restrict__ out)
{
    extern __shared__ float smf[];
    float* sW  = smf;
    float* sy2 = smf + HH * 128;
    int tid = threadIdx.x;
    int n_base = blockIdx.x * 128;

    for (int idx = tid; idx < HH * 32; idx += 256) {
        int k = idx >> 5, q = idx & 31;
        *(float4*)(sW + k*128 + q*4) = *(const float4*)(out_W + (size_t)k * VV + n_base + q*4);
    }
    for (int idx = tid; idx < BB * 64; idx += 256) {
        int bb = idx >> 6, q = idx & 63;
        float4 v = *(const float4*)(g_y2 + bb * HH + q*4);
        float* d = sy2 + bb*257 + q*4;
        d[0] = v.x; d[1] = v.y; d[2] = v.z; d[3] = v.w;
    }
    __syncthreads();

    int bg = tid >> 4, ng = tid & 15;
    int b0 = bg * 4, n0 = ng * 8;
    float acc[4][8];
    #pragma unroll
    for (int r = 0; r < 4; ++r)
        #pragma unroll
        for (int c = 0; c < 8; ++c) acc[r][c] = 0.f;
    for (int k = 0; k < HH; ++k) {
        float4 w0 = *(const float4*)(sW + k*128 + n0);
        float4 w1 = *(const float4*)(sW + k*128 + n0 + 4);
        float wv[8] = {w0.x, w0.y, w0.z, w0.w, w1.x, w1.y, w1.z, w1.w};
        #pragma unroll
        for (int r = 0; r < 4; ++r) {
            float yv = sy2[(b0+r)*257 + k];
            #pragma unroll
            for (int c = 0; c < 8; ++c) acc[r][c] += yv * wv[c];
        }
    }
    #pragma unroll
    for (int r = 0; r < 4; ++r)
        #pragma unroll
        for (int c = 0; c < 8; ++c)
            out[(size_t)(b0+r) * VV + n_base + n0 + c] = acc[r][c] + out_b[n_base + n0 + c];
}

// ---------------- launch ----------------
extern "C" void kernel_launch(void* const* d_in, const int* in_sizes, int n_in,
                              void* d_out, int out_size) {
    (void)in_sizes; (void)n_in; (void)out_size;
    const int*   seq     = (const int*)  d_in[0];
    const float* embed   = (const float*)d_in[1];
    const float* W1      = (const float*)d_in[2];
    const float* b1      = (const float*)d_in[3];
    const float* W2      = (const float*)d_in[4];
    const float* b2      = (const float*)d_in[5];
    const float* gamma   = (const float*)d_in[6];
    const float* beta_ln = (const float*)d_in[7];
    const float* rp_W    = (const float*)d_in[8];
    const float* rp_b    = (const float*)d_in[9];
    const float* out_W   = (const float*)d_in[10];
    const float* out_b   = (const float*)d_in[11];
    float* out = (float*)d_out;

    cudaFuncSetAttribute(k_ffn<1>, cudaFuncAttributeMaxDynamicSharedMemorySize, FFN_SMEM);
    cudaFuncSetAttribute(k_ffn<2>, cudaFuncAttributeMaxDynamicSharedMemorySize, FFN_SMEM);
    cudaFuncSetAttribute(k_scan,   cudaFuncAttributeMaxDynamicSharedMemorySize, SCAN_SMEM_BYTES);
    cudaFuncSetAttribute(k_out,    cudaFuncAttributeMaxDynamicSharedMemorySize, OUT_SMEM_BYTES);

    k_prep<<<512, 256>>>(W1, W2);
    k_split<<<BB * LL * 32 / 256, 256>>>(seq, embed);
    k_ffn<1><<<dim3(4, BB*LL/128), 256, FFN_SMEM>>>(seq, embed, b1);
    k_ffn<2><<<dim3(2, BB*LL/128), 256, FFN_SMEM>>>(seq, embed, b2);
    k_ln<<<BB * LL / 8, 256>>>(gamma, beta_ln);
    k_scan<<<BB * 2, 256, SCAN_SMEM_BYTES>>>();
    k_read1<<<BB, 256>>>();
    k_read2<<<BB, HH>>>(rp_W, rp_b);
    k_out<<<VV / 128, 256, OUT_SMEM_BYTES>>>(out_W, out_b, out);
}

// round 10
// speedup vs baseline: 3.8193x; 1.3796x over previous
#include <cuda_runtime.h>
#include <cuda_fp16.h>
#include <math.h>
#include <stdint.h>

static constexpr int BB = 64;
static constexpr int LL = 2048;
static constexpr int HH = 256;
static constexpr int VV = 32000;
static constexpr int TT = LL - 1;
static constexpr float BETA = 0.9f;
static constexpr float OMB  = 0.1f;
static constexpr int CH = 32;

// ---------------- scratch ----------------
__device__ float  g_h [(size_t)BB*LL*HH];
__device__ __half g_af[(size_t)BB*LL*HH];       // tiled-swizzled fp16 A for ffn1
__device__ __half g_ff[(size_t)BB*LL*2*HH];     // tiled-swizzled fp16 A for ffn2
__device__ __half g_w1t[512*256];               // tiled-swizzled W1^T
__device__ __half g_w2t[256*512];               // tiled-swizzled W2^T
__device__ float  g_M [(size_t)BB*HH*HH];
__device__ float  g_y [BB*HH];
__device__ float  g_y2[BB*HH];

#define SWZ(o)  ((o) ^ (((o) >> 3) & 0x70))   // 128B rows
#define SWZ5(o) ((o) ^ (((o) >> 5) & 0x70))   // 512B rows

__device__ __forceinline__ uint32_t smem_u32(const void* p) {
    uint32_t a;
    asm("{ .reg .u64 t; cvta.to.shared.u64 t, %1; cvt.u32.u64 %0, t; }" : "=r"(a) : "l"(p));
    return a;
}
__device__ __forceinline__ uint32_t packh2(float a, float b) {
    __half2 t = __floats2half2_rn(a, b);
    return *reinterpret_cast<uint32_t*>(&t);
}
__device__ __forceinline__ void ldsm_x4(uint32_t* r, uint32_t addr) {
    asm volatile("ldmatrix.sync.aligned.m8n8.x4.shared.b16 {%0,%1,%2,%3}, [%4];"
        : "=r"(r[0]), "=r"(r[1]), "=r"(r[2]), "=r"(r[3]) : "r"(addr));
}
__device__ __forceinline__ void ldsm_x4t(uint32_t* r, uint32_t addr) {
    asm volatile("ldmatrix.sync.aligned.m8n8.x4.trans.shared.b16 {%0,%1,%2,%3}, [%4];"
        : "=r"(r[0]), "=r"(r[1]), "=r"(r[2]), "=r"(r[3]) : "r"(addr));
}
__device__ __forceinline__ void ldsm_x2(uint32_t* r, uint32_t addr) {
    asm volatile("ldmatrix.sync.aligned.m8n8.x2.shared.b16 {%0,%1}, [%2];"
        : "=r"(r[0]), "=r"(r[1]) : "r"(addr));
}
__device__ __forceinline__ void mma_f16(float* d, const uint32_t* a, uint32_t b0, uint32_t b1) {
    asm volatile("mma.sync.aligned.m16n8k16.row.col.f32.f16.f16.f32 "
        "{%0,%1,%2,%3}, {%4,%5,%6,%7}, {%8,%9}, {%0,%1,%2,%3};"
        : "+f"(d[0]), "+f"(d[1]), "+f"(d[2]), "+f"(d[3])
        : "r"(a[0]), "r"(a[1]), "r"(a[2]), "r"(a[3]), "r"(b0), "r"(b1));
}

#define MBAR_INIT(a, cnt) \
    asm volatile("mbarrier.init.shared.b64 [%0], %1;" :: "r"((uint32_t)(a)), "r"((uint32_t)(cnt)) : "memory")
#define MBAR_TX(a, bytes) \
    asm volatile("mbarrier.arrive.expect_tx.shared.b64 _, [%0], %1;" :: "r"((uint32_t)(a)), "r"((uint32_t)(bytes)) : "memory")
#define BULK(dst, src, bytes, mbar) \
    asm volatile("cp.async.bulk.shared::cta.global.mbarrier::complete_tx::bytes [%0], [%1], %2, [%3];" \
        :: "r"((uint32_t)(dst)), "l"(src), "r"((uint32_t)(bytes)), "r"((uint32_t)(mbar)) : "memory")
#define MBAR_WAIT(a, par) do {                                                    \
    uint32_t _m = (uint32_t)(a); uint32_t _p = (uint32_t)(par); uint32_t _d;      \
    asm volatile("{\n\t.reg .pred p;\n\t"                                         \
        "mbarrier.try_wait.parity.acquire.cta.shared::cta.b64 p, [%1], %2;\n\t"   \
        "selp.b32 %0, 1, 0, p;\n\t}"                                              \
        : "=r"(_d) : "r"(_m), "r"(_p) : "memory");                                \
    if (!_d) {                                                                    \
        asm volatile("{\n\t.reg .pred P1;\n\t"                                    \
            "WL_%=:\n\t"                                                          \
            "mbarrier.try_wait.parity.acquire.cta.shared::cta.b64 P1, [%0], %1, 0x989680;\n\t" \
            "@P1 bra.uni WD_%=;\n\t"                                              \
            "bra.uni WL_%=;\n\t"                                                  \
            "WD_%=:\n\t}"                                                         \
            :: "r"(_m), "r"(_p) : "memory");                                      \
    }                                                                             \
} while (0)

// ---------------- 0a. weights -> fp16, tiled-swizzled 16KB tiles ----------------
__global__ void k_prep(const float* __restrict__ W1, const float* __restrict__ W2) {
    int idx = blockIdx.x * blockDim.x + threadIdx.x;   // 0..131071
    {
        int n = idx >> 8, k = idx & 255;
        __half v = __float2half_rn(W1[k * 512 + n]);
        size_t off = (((size_t)(n >> 7) * 4 + (k >> 6)) << 14)
                   + SWZ((uint32_t)((n & 127) * 128 + (k & 63) * 2));
        *(__half*)((char*)g_w1t + off) = v;
    }
    {
        int n = idx >> 9, k = idx & 511;
        __half v = __float2half_rn(W2[k * 256 + n]);
        size_t off = (((size_t)(n >> 7) * 8 + (k >> 6)) << 14)
                   + SWZ((uint32_t)((n & 127) * 128 + (k & 63) * 2));
        *(__half*)((char*)g_w2t + off) = v;
    }
}

// ---------------- 0b. gather -> fp16 tiled-swizzled ----------------
__global__ void k_split(const int* __restrict__ seq, const float* __restrict__ embed) {
    size_t idx = (size_t)blockIdx.x * blockDim.x + threadIdx.x;   // B*L*32
    int row = (int)(idx >> 5), g = (int)(idx & 31);
    int tok = seq[row];
    const float4* src = (const float4*)(embed + (size_t)tok * HH + g * 8);
    float4 v0 = src[0], v1 = src[1];
    uint4 o = make_uint4(packh2(v0.x, v0.y), packh2(v0.z, v0.w),
                         packh2(v1.x, v1.y), packh2(v1.z, v1.w));
    int mt = row >> 7, c = g >> 3;
    size_t off = (((size_t)mt * 4 + c) << 14)
               + SWZ((uint32_t)((row & 127) * 128 + (g & 7) * 16));
    *(uint4*)((char*)g_af + off) = o;
}

// ---------------- 1+2. FFN: fp16 HMMA + cp.async.bulk 3-stage ----------------
static constexpr int FFN_SMEM = 1024 + 3 * 32768 + 64;   // 99392

__device__ __forceinline__ void ffn_compute(uint32_t aB, uint32_t bB,
                                            int wm, int wn, int lid, float (&acc)[4][4][4])
{
    #pragma unroll
    for (int ks = 0; ks < 4; ++ks) {
        uint32_t colA = ks * 32 + ((lid >> 4) << 4);
        uint32_t ah[4][4];
        #pragma unroll
        for (int mf = 0; mf < 4; ++mf) {
            uint32_t row = wm * 64 + mf * 16 + (lid & 15);
            ldsm_x4(ah[mf], aB + SWZ(row * 128 + colA));
        }
        uint32_t bh[2][4];
        #pragma unroll
        for (int nf = 0; nf < 2; ++nf) {
            uint32_t row = wn * 32 + nf * 16 + ((lid >> 4) << 3) + (lid & 7);
            uint32_t colB = ks * 32 + (((lid >> 3) & 1) << 4);
            ldsm_x4(bh[nf], bB + SWZ(row * 128 + colB));
        }
        #pragma unroll
        for (int mf = 0; mf < 4; ++mf)
            #pragma unroll
            for (int nf = 0; nf < 2; ++nf)
                #pragma unroll
                for (int j = 0; j < 2; ++j)
                    mma_f16(acc[mf][nf*2+j], ah[mf], bh[nf][j*2], bh[nf][j*2+1]);
    }
}

template<int PHASE>
__global__ __launch_bounds__(256, 2) void k_ffn(
    const int* __restrict__ seq, const float* __restrict__ embed,
    const float* __restrict__ bias)
{
    constexpr int NC = (PHASE == 1) ? 4 : 8;

    extern __shared__ char sm[];
    int*   sseq  = (int*)sm;
    float* sbias = (float*)(sm + 512);
    const uint32_t sb = smem_u32(sm);
    const uint32_t stg0 = sb + 1024;
    const uint32_t mb   = sb + 1024 + 3 * 32768;

    const int tid = threadIdx.x, wid = tid >> 5, lid = tid & 31;
    const int wm = wid & 1, wn = wid >> 1;
    const int mt = blockIdx.y, nb0 = blockIdx.x * 128;

    const char* Atl = (const char*)((PHASE == 1) ? (const void*)g_af : (const void*)g_ff)
                    + (((size_t)mt * NC) << 14);
    const char* Btl = (const char*)((PHASE == 1) ? (const void*)g_w1t : (const void*)g_w2t)
                    + (((size_t)blockIdx.x * NC) << 14);

    if (tid < 128) {
        sbias[tid] = bias[nb0 + tid];
        if (PHASE == 2) sseq[tid] = seq[mt * 128 + tid];
    }
    if (tid == 0) { MBAR_INIT(mb, 1); MBAR_INIT(mb + 8, 1); MBAR_INIT(mb + 16, 1); }
    __syncthreads();

    if (tid == 0) {
        #pragma unroll
        for (int p = 0; p < 3; ++p) {
            uint32_t stp = stg0 + p * 32768;
            MBAR_TX(mb + p * 8, 32768);
            BULK(stp, Atl + ((size_t)p << 14), 16384, mb + p * 8);
            BULK(stp + 16384, Btl + ((size_t)p << 14), 16384, mb + p * 8);
        }
    }

    float acc[4][4][4];
    #pragma unroll
    for (int a = 0; a < 4; ++a)
        #pragma unroll
        for (int b = 0; b < 4; ++b)
            #pragma unroll
            for (int c = 0; c < 4; ++c) acc[a][b][c] = 0.f;

    for (int c = 0; c < NC; ++c) {
        int s = c % 3;
        uint32_t stg = stg0 + s * 32768;
        MBAR_WAIT(mb + s * 8, (c / 3) & 1);
        ffn_compute(stg, stg + 16384, wm, wn, lid, acc);
        __syncthreads();
        if (tid == 0 && c + 3 < NC) {
            MBAR_TX(mb + s * 8, 32768);
            BULK(stg, Atl + ((size_t)(c + 3) << 14), 16384, mb + s * 8);
            BULK(stg + 16384, Btl + ((size_t)(c + 3) << 14), 16384, mb + s * 8);
        }
    }

    const int qm = lid >> 2, qn = (lid & 3) * 2;
    if (PHASE == 1) {
        uint32_t* SH = (uint32_t*)(sm + 1024);
        #pragma unroll
        for (int mf = 0; mf < 4; ++mf)
            #pragma unroll
            for (int nf = 0; nf < 2; ++nf)
                #pragma unroll
                for (int j = 0; j < 2; ++j) {
                    const float* d = acc[mf][nf*2+j];
                    int nl = wn * 32 + nf * 16 + j * 8 + qn;
                    #pragma unroll
                    for (int hh = 0; hh < 2; ++hh) {
                        int ml = wm * 64 + mf * 16 + qm + hh * 8;
                        float v0 = fmaxf(d[hh*2+0] + sbias[nl],   0.f);
                        float v1 = fmaxf(d[hh*2+1] + sbias[nl+1], 0.f);
                        SH[ml * 64 + (nl >> 1)] = packh2(v0, v1);
                    }
                }
        __syncthreads();
        char* gff = (char*)g_ff;
        #pragma unroll
        for (int t = 0; t < 8; ++t) {
            int idx = t * 256 + tid;
            int tile = idx >> 10, rem = idx & 1023;
            int r = rem >> 3, j = rem & 7;
            uint4 v = ((const uint4*)SH)[r * 16 + tile * 8 + j];
            size_t off = (((size_t)mt * 8 + blockIdx.x * 2 + tile) << 14)
                       + SWZ((uint32_t)(r * 128 + j * 16));
            *(uint4*)(gff + off) = v;
        }
    } else {
        float* SF = (float*)(sm + 1024);
        #pragma unroll
        for (int mf = 0; mf < 4; ++mf)
            #pragma unroll
            for (int nf = 0; nf < 2; ++nf)
                #pragma unroll
                for (int j = 0; j < 2; ++j) {
                    const float* d = acc[mf][nf*2+j];
                    int nl = wn * 32 + nf * 16 + j * 8 + qn;
                    #pragma unroll
                    for (int hh = 0; hh < 2; ++hh) {
                        int ml = wm * 64 + mf * 16 + qm + hh * 8;
                        SF[ml * 128 + nl]     = d[hh*2+0] + sbias[nl];
                        SF[ml * 128 + nl + 1] = d[hh*2+1] + sbias[nl+1];
                    }
                }
        __syncthreads();
        int row = tid >> 1, part = tid & 1;
        int tok = sseq[row];
        const float4* ep = (const float4*)(embed + (size_t)tok * HH + nb0);
        const float4* sfp = (const float4*)(SF + row * 128);
        float4* gp = (float4*)(g_h + ((size_t)mt * 128 + row) * HH + nb0);
        #pragma unroll
        for (int j = 0; j < 16; ++j) {
            int c4 = part * 16 + j;
            float4 f = sfp[c4];
            float4 e = ep[c4];
            f.x += e.x; f.y += e.y; f.z += e.z; f.w += e.w;
            gp[c4] = f;
        }
    }
}

// ---------------- 3. LayerNorm (unchanged) ----------------
__global__ void k_ln(const float* __restrict__ gamma, const float* __restrict__ beta_ln) {
    int warp = threadIdx.x >> 5, lane = threadIdx.x & 31;
    size_t row = (size_t)blockIdx.x * 8 + warp;
    float4* xp = (float4*)(g_h + row * HH);
    float4 a = xp[lane * 2];
    float4 b = xp[lane * 2 + 1];
    float s = a.x + a.y + a.z + a.w + b.x + b.y + b.z + b.w;
    #pragma unroll
    for (int o = 16; o; o >>= 1) s += __shfl_xor_sync(0xffffffffu, s, o);
    float mu = s * (1.0f / HH);
    float dx[8] = {a.x-mu, a.y-mu, a.z-mu, a.w-mu, b.x-mu, b.y-mu, b.z-mu, b.w-mu};
    float v = 0.f;
    #pragma unroll
    for (int q = 0; q < 8; ++q) v += dx[q] * dx[q];
    #pragma unroll
    for (int o = 16; o; o >>= 1) v += __shfl_xor_sync(0xffffffffu, v, o);
    float inv = rsqrtf(v * (1.0f / HH) + 1e-5f);
    float4 g0 = ((const float4*)gamma)[lane * 2];
    float4 g1 = ((const float4*)gamma)[lane * 2 + 1];
    float4 t0 = ((const float4*)beta_ln)[lane * 2];
    float4 t1 = ((const float4*)beta_ln)[lane * 2 + 1];
    float4 o0, o1;
    o0.x = dx[0]*inv*g0.x + t0.x; o0.y = dx[1]*inv*g0.y + t0.y;
    o0.z = dx[2]*inv*g0.z + t0.z; o0.w = dx[3]*inv*g0.w + t0.w;
    o1.x = dx[4]*inv*g1.x + t1.x; o1.y = dx[5]*inv*g1.y + t1.y;
    o1.z = dx[6]*inv*g1.z + t1.z; o1.w = dx[7]*inv*g1.w + t1.w;
    xp[lane * 2]     = o0;
    xp[lane * 2 + 1] = o1;
}

// ---------------- 4. scan: single-term fp16 HMMA chunked delta rule ----------------
static constexpr uint32_t OFF_MH  = 0;        // [128][512B] fp16 swz5
static constexpr uint32_t OFF_KH  = 65536;    // [32][512B] fp16 swz5
static constexpr uint32_t OFF_SD  = 81920;    // [32][128] f32 raw U
static constexpr uint32_t OFF_DT  = 98304;    // [128][80B] fp16 weighted d^T
static constexpr uint32_t OFF_G   = 108544;   // [32][36] f32
static constexpr uint32_t OFF_A   = 113152;   // [32][32] f32
static constexpr uint32_t OFF_SC  = 117248;   // sc, ct, wv, spw
static constexpr int SCAN_SMEM_BYTES = 131584; // >= 131072 final staging

__global__ __launch_bounds__(256, 1) void k_scan() {
    extern __shared__ char smc[];
    const uint32_t sb = smem_u32(smc);
    const uint32_t MH = sb + OFF_MH;
    const uint32_t KH = sb + OFF_KH;
    float* sD  = (float*)(smc + OFF_SD);
    float* sG  = (float*)(smc + OFF_G);
    float* sA  = (float*)(smc + OFF_A);
    float* sc  = (float*)(smc + OFF_SC);
    float* ct  = sc + 32;
    float* wv  = ct + 32;
    float* spw = wv + 32;

    const int tid = threadIdx.x, wid = tid >> 5, lid = tid & 31;
    const int qm = lid >> 2, qn = (lid & 3) * 2;
    const int b  = blockIdx.x >> 1;
    const int r0 = (blockIdx.x & 1) * 128;
    const float* hb = g_h + (size_t)b * LL * HH;

    for (int i = tid; i < 65536 / 16; i += 256)
        ((uint4*)(smc + OFF_MH))[i] = make_uint4(0, 0, 0, 0);
    if (tid == 0) {
        spw[0] = 1.f;
        for (int i = 1; i <= CH; ++i) spw[i] = spw[i-1] * BETA;
    }
    __syncthreads();

    float acc[32][4];
    #pragma unroll
    for (int f = 0; f < 32; ++f)
        #pragma unroll
        for (int q = 0; q < 4; ++q) acc[f][q] = 0.f;

    const int klt = tid >> 3, kq = tid & 7;

    for (int t0 = 0; t0 < TT; t0 += CH) {
        const int Cc = min(CH, TT - t0);
        __syncthreads();

        // ---- (a) K chunk -> fp16 swz5 ----
        {
            const float* src = hb + (size_t)(t0 + klt) * HH + kq * 32;
            bool pad = (klt >= Cc);
            #pragma unroll
            for (int g = 0; g < 4; ++g) {
                float f[8];
                if (pad) {
                    #pragma unroll
                    for (int q = 0; q < 8; ++q) f[q] = 0.f;
                } else {
                    float4 v0 = *(const float4*)(src + g*8);
                    float4 v1 = *(const float4*)(src + g*8 + 4);
                    f[0]=v0.x; f[1]=v0.y; f[2]=v0.z; f[3]=v0.w;
                    f[4]=v1.x; f[5]=v1.y; f[6]=v1.z; f[7]=v1.w;
                }
                uint32_t off = SWZ5((uint32_t)(klt * 512 + (kq * 32 + g * 8) * 2));
                *(uint4*)(smc + OFF_KH + off) =
                    make_uint4(packh2(f[0], f[1]), packh2(f[2], f[3]),
                               packh2(f[4], f[5]), packh2(f[6], f[7]));
            }
        }
        __syncthreads();

        // ---- (b) Gram G = K K^T ----
        {
            float gacc[4] = {0.f, 0.f, 0.f, 0.f};
            const int mh = wid & 1, nq = wid >> 1;
            const uint32_t arow = (uint32_t)(16 * mh + (lid & 15)) * 512;
            const uint32_t asel = (uint32_t)((lid >> 4) << 4);
            const uint32_t brow = (uint32_t)(8 * nq + (lid & 7)) * 512;
            const uint32_t bsel = (uint32_t)(((lid >> 3) & 1) << 4);
            #pragma unroll
            for (int ks = 0; ks < 16; ++ks) {
                uint32_t ca = ks * 32;
                uint32_t ag[4], gb[2];
                ldsm_x4(ag, KH + SWZ5(arow + ca + asel));
                ldsm_x2(gb, KH + SWZ5(brow + ca + bsel));
                mma_f16(gacc, ag, gb[0], gb[1]);
            }
            int t = 16 * mh + qm, s = 8 * nq + qn;
            sG[t*36 + s] = gacc[0]; sG[t*36 + s + 1] = gacc[1];
            sG[(t+8)*36 + s] = gacc[2]; sG[(t+8)*36 + s + 1] = gacc[3];
        }
        __syncthreads();

        if (tid < 32) {
            float g = sG[tid*36 + tid];
            float s = 1.0f / (g + 1e-6f);
            sc[tid] = s;
            ct[tid] = s * spw[tid];
            wv[tid] = (tid < Cc) ? OMB * spw[Cc - 1 - tid] : 0.f;
        }
        __syncthreads();

        // ---- (c) coupling coefs + (d) U = M K^T ----
        for (int p = tid; p < 1024; p += 256) {
            int t = p >> 5, s = p & 31;
            if (s < t) sA[p] = sG[t*36 + s] * sc[t] * OMB * spw[t - 1 - s];
        }
        {
            float uacc[4][4];
            #pragma unroll
            for (int f = 0; f < 4; ++f)
                #pragma unroll
                for (int q = 0; q < 4; ++q) uacc[f][q] = 0.f;
            const uint32_t mrow = (uint32_t)(16 * wid + (lid & 15)) * 512;
            const uint32_t asel = (uint32_t)((lid >> 4) << 4);
            const uint32_t brow0 = (uint32_t)(((lid >> 4) << 3) + (lid & 7)) * 512;
            const uint32_t brow1 = brow0 + 16 * 512;
            const uint32_t bsel = (uint32_t)(((lid >> 3) & 1) << 4);
            #pragma unroll
            for (int ks = 0; ks < 16; ++ks) {
                uint32_t ca = ks * 32;
                uint32_t am[4], b0[4], b1[4];
                ldsm_x4(am, MH + SWZ5(mrow + ca + asel));
                ldsm_x4(b0, KH + SWZ5(brow0 + ca + bsel));
                ldsm_x4(b1, KH + SWZ5(brow1 + ca + bsel));
                #pragma unroll
                for (int f = 0; f < 4; ++f) {
                    const uint32_t* bh = (f < 2) ? b0 : b1;
                    int j = (f & 1) * 2;
                    mma_f16(uacc[f], am, bh[j], bh[j+1]);
                }
            }
            int i = 16 * wid + qm;
            #pragma unroll
            for (int f = 0; f < 4; ++f) {
                int lt = 8 * f + qn;
                sD[lt*128 + i]           = uacc[f][0];
                sD[(lt+1)*128 + i]       = uacc[f][1];
                sD[lt*128 + i + 8]       = uacc[f][2];
                sD[(lt+1)*128 + i + 8]   = uacc[f][3];
            }
        }
        __syncthreads();

        // ---- (e) triangular solve; rhs = fp32 h from global (L1/L2 hot) ----
        if (tid < 128) {
            const int i = tid;
            float d[CH];
            #pragma unroll
            for (int t = 0; t < CH; ++t) {
                float rhs = (t < Cc) ? hb[(size_t)(t0 + t) * HH + r0 + i] : 0.f;
                d[t] = rhs - ct[t] * sD[t*128 + i];
            }
            #pragma unroll
            for (int s = 0; s < CH - 1; ++s)
                #pragma unroll
                for (int t = s + 1; t < CH; ++t)
                    d[t] -= sA[t*32 + s] * d[s];
            #pragma unroll
            for (int s = 0; s < CH; s += 2)
                *(uint32_t*)(smc + OFF_DT + i*80 + s*2) =
                    packh2(d[s] * wv[s], d[s+1] * wv[s+1]);
        }
        __syncthreads();

        // ---- (f) M update: acc = beta^Cc * acc + dT^T @ K ----
        {
            float bc = spw[Cc];
            #pragma unroll
            for (int f = 0; f < 32; ++f)
                #pragma unroll
                for (int q = 0; q < 4; ++q) acc[f][q] *= bc;
            const uint32_t adbase = (uint32_t)(16 * wid + (lid & 15)) * 80
                                  + (uint32_t)((lid >> 4) << 4);
            const uint32_t tsel = (uint32_t)((lid >> 4) << 3) * 2;
            #pragma unroll
            for (int ks = 0; ks < 2; ++ks) {
                uint32_t ad[4];
                ldsm_x4(ad, sb + OFF_DT + adbase + ks * 32);
                uint32_t trow = (uint32_t)(ks * 16 + (lid & 15)) * 512;
                #pragma unroll
                for (int jg = 0; jg < 16; ++jg) {
                    uint32_t o = SWZ5(trow + jg * 32 + tsel);
                    uint32_t bt[4];
                    ldsm_x4t(bt, KH + o);
                    mma_f16(acc[jg*2],   ad, bt[0], bt[1]);
                    mma_f16(acc[jg*2+1], ad, bt[2], bt[3]);
                }
            }
        }

        // ---- (g) publish M fp16 for next chunk ----
        if (t0 + CH < TT) {
            int r1 = 16 * wid + qm;
            #pragma unroll
            for (int f = 0; f < 32; ++f) {
                int c = f * 8 + qn;
                *(uint32_t*)(smc + OFF_MH + SWZ5((uint32_t)(r1 * 512 + c * 2))) =
                    packh2(acc[f][0], acc[f][1]);
                *(uint32_t*)(smc + OFF_MH + SWZ5((uint32_t)((r1 + 8) * 512 + c * 2))) =
                    packh2(acc[f][2], acc[f][3]);
            }
        }
    }

    // ---- final: stage fp32 M, write g_M ----
    __syncthreads();
    {
        float* SF = (float*)smc;
        int r1 = 16 * wid + qm;
        #pragma unroll
        for (int f = 0; f < 32; ++f) {
            int c = f * 8 + qn;
            SF[r1*256 + c]       = acc[f][0];
            SF[r1*256 + c + 1]   = acc[f][1];
            SF[(r1+8)*256 + c]   = acc[f][2];
            SF[(r1+8)*256 + c+1] = acc[f][3];
        }
        __syncthreads();
        const float4* sp = (const float4*)SF;
        for (int q = tid; q < 128 * 64; q += 256) {
            int i = q >> 6, j4 = q & 63;
            ((float4*)(g_M + ((size_t)b * HH + r0 + i) * HH))[j4] = sp[i*64 + j4];
        }
    }
}

// ---------------- 5-7. readout (unchanged) ----------------
__global__ void k_read1() {
    int b = blockIdx.x;
    int tid = threadIdx.x;
    __shared__ float hl[HH];
    hl[tid] = g_h[((size_t)b * LL + (LL - 1)) * HH + tid];
    __syncthreads();
    int w = tid >> 5, lane = tid & 31;
    for (int i = w; i < HH; i += 8) {
        const float* Mr = g_M + ((size_t)b * HH + i) * HH;
        float s = 0.f;
        #pragma unroll
        for (int j = lane; j < HH; j += 32) s += Mr[j] * hl[j];
        #pragma unroll
        for (int o = 16; o; o >>= 1) s += __shfl_xor_sync(0xffffffffu, s, o);
        if (lane == 0) g_y[b * HH + i] = s;
    }
}
__global__ void k_read2(const float* __restrict__ rp_W, const float* __restrict__ rp_b) {
    int b = blockIdx.x, n = threadIdx.x;
    __shared__ float ys[HH];
    ys[n] = g_y[b * HH + n];
    __syncthreads();
    float acc = rp_b[n];
    #pragma unroll 4
    for (int k = 0; k < HH; ++k) acc += ys[k] * rp_W[k * HH + n];
    g_y2[b * HH + n] = acc;
}

static constexpr int OUT_SMEM_BYTES = (HH * 128 + BB * 257) * 4;

__global__ __launch_bounds__(256) void k_out(
    const float* __restrict__ out_W, const float* __restrict__ out_b,
    float* __restrict__ out)
{
    extern __shared__ float smf[];
    float* sW  = smf;
    float* sy2 = smf + HH * 128;
    int tid = threadIdx.x;
    int n_base = blockIdx.x * 128;

    for (int idx = tid; idx < HH * 32; idx += 256) {
        int k = idx >> 5, q = idx & 31;
        *(float4*)(sW + k*128 + q*4) = *(const float4*)(out_W + (size_t)k * VV + n_base + q*4);
    }
    for (int idx = tid; idx < BB * 64; idx += 256) {
        int bb = idx >> 6, q = idx & 63;
        float4 v = *(const float4*)(g_y2 + bb * HH + q*4);
        float* d = sy2 + bb*257 + q*4;
        d[0] = v.x; d[1] = v.y; d[2] = v.z; d[3] = v.w;
    }
    __syncthreads();

    int bg = tid >> 4, ng = tid & 15;
    int b0 = bg * 4, n0 = ng * 8;
    float acc[4][8];
    #pragma unroll
    for (int r = 0; r < 4; ++r)
        #pragma unroll
        for (int c = 0; c < 8; ++c) acc[r][c] = 0.f;
    for (int k = 0; k < HH; ++k) {
        float4 w0 = *(const float4*)(sW + k*128 + n0);
        float4 w1 = *(const float4*)(sW + k*128 + n0 + 4);
        float wv[8] = {w0.x, w0.y, w0.z, w0.w, w1.x, w1.y, w1.z, w1.w};
        #pragma unroll
        for (int r = 0; r < 4; ++r) {
            float yv = sy2[(b0+r)*257 + k];
            #pragma unroll
            for (int c = 0; c < 8; ++c) acc[r][c] += yv * wv[c];
        }
    }
    #pragma unroll
    for (int r = 0; r < 4; ++r)
        #pragma unroll
        for (int c = 0; c < 8; ++c)
            out[(size_t)(b0+r) * VV + n_base + n0 + c] = acc[r][c] + out_b[n_base + n0 + c];
}

// ---------------- launch ----------------
extern "C" void kernel_launch(void* const* d_in, const int* in_sizes, int n_in,
                              void* d_out, int out_size) {
    (void)in_sizes; (void)n_in; (void)out_size;
    const int*   seq     = (const int*)  d_in[0];
    const float* embed   = (const float*)d_in[1];
    const float* W1      = (const float*)d_in[2];
    const float* b1      = (const float*)d_in[3];
    const float* W2      = (const float*)d_in[4];
    const float* b2      = (const float*)d_in[5];
    const float* gamma   = (const float*)d_in[6];
    const float* beta_ln = (const float*)d_in[7];
    const float* rp_W    = (const float*)d_in[8];
    const float* rp_b    = (const float*)d_in[9];
    const float* out_W   = (const float*)d_in[10];
    const float* out_b   = (const float*)d_in[11];
    float* out = (float*)d_out;

    cudaFuncSetAttribute(k_ffn<1>, cudaFuncAttributeMaxDynamicSharedMemorySize, FFN_SMEM);
    cudaFuncSetAttribute(k_ffn<2>, cudaFuncAttributeMaxDynamicSharedMemorySize, FFN_SMEM);
    cudaFuncSetAttribute(k_scan,   cudaFuncAttributeMaxDynamicSharedMemorySize, SCAN_SMEM_BYTES);
    cudaFuncSetAttribute(k_out,    cudaFuncAttributeMaxDynamicSharedMemorySize, OUT_SMEM_BYTES);

    k_prep<<<512, 256>>>(W1, W2);
    k_split<<<BB * LL * 32 / 256, 256>>>(seq, embed);
    k_ffn<1><<<dim3(4, BB*LL/128), 256, FFN_SMEM>>>(seq, embed, b1);
    k_ffn<2><<<dim3(2, BB*LL/128), 256, FFN_SMEM>>>(seq, embed, b2);
    k_ln<<<BB * LL / 8, 256>>>(gamma, beta_ln);
    k_scan<<<BB * 2, 256, SCAN_SMEM_BYTES>>>();
    k_read1<<<BB, 256>>>();
    k_read2<<<BB, HH>>>(rp_W, rp_b);
    k_out<<<VV / 128, 256, OUT_SMEM_BYTES>>>(out_W, out_b, out);
}